// round 3
// baseline (speedup 1.0000x reference)
#include <cuda_runtime.h>
#include <math.h>

#define NN 100000
#define EE 600000

// ---------------- static scratch (no allocations allowed) ----------------
__device__ int   g_is64;
__device__ int   g_deg[NN];
__device__ int   g_cur[NN];
__device__ int   g_rowstart[NN + 1];
__device__ int   g_col[EE];
__device__ float g_mean[(size_t)NN * 256];
__device__ float g_h1[(size_t)NN * 256];
__device__ float g_h2[(size_t)NN * 128];
__device__ float g_h3[(size_t)NN * 64];

__device__ __forceinline__ float* devbuf(int id) {
    switch (id) {
        case 0: return g_mean;
        case 1: return g_h1;
        case 2: return g_h2;
        default: return g_h3;
    }
}

// ---------------- dtype probe: int32 vs int64 edge_index ----------------
// For little-endian int64 values < 2^31, every odd 32-bit word is 0.
// For int32 data the odd words are random node ids (all-zero prob ~1e-320).
__global__ void k_detect(const int* __restrict__ w) {
    if (threadIdx.x == 0 && blockIdx.x == 0) {
        int is64 = 1;
        for (int i = 0; i < 64; i++) {
            if (w[2 * i + 1] != 0) { is64 = 0; break; }
        }
        g_is64 = is64;
    }
}

__device__ __forceinline__ int edge_src(const int* w, int E, int e) {
    return g_is64 ? w[2 * e] : w[e];
}
__device__ __forceinline__ int edge_dst(const int* w, int E, int e) {
    return g_is64 ? w[2 * (E + e)] : w[E + e];
}

// ---------------- CSR build ----------------
__global__ void k_zero_counts() {
    int i = blockIdx.x * blockDim.x + threadIdx.x;
    if (i < NN) { g_deg[i] = 0; g_cur[i] = 0; }
}

__global__ void k_count(const int* __restrict__ w, int E) {
    int e = blockIdx.x * blockDim.x + threadIdx.x;
    if (e < E) {
        int dst = edge_dst(w, E, e);
        atomicAdd(&g_deg[dst], 1);
    }
}

// single-block exclusive scan over g_deg -> g_rowstart (N=100000, cheap)
__global__ void k_scan(int n) {
    __shared__ int part[1024];
    int t = threadIdx.x;
    int chunk = (n + 1023) / 1024;
    int begin = t * chunk;
    int end   = min(begin + chunk, n);
    int s = 0;
    for (int i = begin; i < end; i++) s += g_deg[i];
    part[t] = s;
    __syncthreads();
    for (int off = 1; off < 1024; off <<= 1) {
        int v = (t >= off) ? part[t - off] : 0;
        __syncthreads();
        part[t] += v;
        __syncthreads();
    }
    int base = (t == 0) ? 0 : part[t - 1];
    for (int i = begin; i < end; i++) {
        g_rowstart[i] = base;
        base += g_deg[i];
    }
    if (t == 1023) g_rowstart[n] = part[1023];
}

__global__ void k_fill(const int* __restrict__ w, int E) {
    int e = blockIdx.x * blockDim.x + threadIdx.x;
    if (e < E) {
        int src = edge_src(w, E, e);
        int dst = edge_dst(w, E, e);
        int pos = g_rowstart[dst] + atomicAdd(&g_cur[dst], 1);
        g_col[pos] = src;
    }
}

// ---------------- mean aggregation: one warp per node ----------------
template <int C>
__global__ void k_agg(const float* __restrict__ ext, int src_id) {
    const float* feat = ext ? ext : devbuf(src_id);
    int gw   = (blockIdx.x * blockDim.x + threadIdx.x) >> 5;
    int lane = threadIdx.x & 31;
    if (gw >= NN) return;
    int s = g_rowstart[gw];
    int e = g_rowstart[gw + 1];
    constexpr int V = C / 128;
    float4 acc[V];
#pragma unroll
    for (int v = 0; v < V; v++) acc[v] = make_float4(0.f, 0.f, 0.f, 0.f);
    for (int i = s; i < e; i++) {
        int nb = g_col[i];
        const float4* row = (const float4*)(feat + (size_t)nb * C);
#pragma unroll
        for (int v = 0; v < V; v++) {
            float4 r = row[lane + 32 * v];
            acc[v].x += r.x; acc[v].y += r.y; acc[v].z += r.z; acc[v].w += r.w;
        }
    }
    float inv = 1.0f / (float)max(e - s, 1);
    float4* o = (float4*)(g_mean + (size_t)gw * C);
#pragma unroll
    for (int v = 0; v < V; v++) {
        float4 r;
        r.x = acc[v].x * inv; r.y = acc[v].y * inv;
        r.z = acc[v].z * inv; r.w = acc[v].w * inv;
        o[lane + 32 * v] = r;
    }
}

// ---------------- fused dual GEMM: out = mean@B0 + A1@B1 + bias (+relu) ----------------
__global__ void __launch_bounds__(256)
k_gemm(const float* __restrict__ A1ext, int a1_id,
       const float* __restrict__ B0, const float* __restrict__ B1,
       const float* __restrict__ bias, int out_id,
       int M, int N, int K, int do_relu) {
    const float* A0 = g_mean;
    const float* A1 = A1ext ? A1ext : devbuf(a1_id);
    float* out = devbuf(out_id);

    constexpr int BM = 64, BN = 64, BK = 16;
    __shared__ float As[BK][BM + 4];
    __shared__ float Bs[BK][BN + 4];

    int tid = threadIdx.x;
    int ty = tid >> 4;
    int tx = tid & 15;

    int ar = tid >> 2;
    int ac = (tid & 3) * 4;
    int br = tid >> 4;
    int bc = (tid & 15) * 4;

    int blockRow = blockIdx.x * BM;
    int blockCol = blockIdx.y * BN;

    float c[4][4];
#pragma unroll
    for (int i = 0; i < 4; i++)
#pragma unroll
        for (int j = 0; j < 4; j++) c[i][j] = 0.f;

    int K2 = 2 * K;
    for (int kk = 0; kk < K2; kk += BK) {
        {
            int grow = blockRow + ar;
            int gk   = kk + ac;
            float4 av = make_float4(0.f, 0.f, 0.f, 0.f);
            if (grow < M) {
                const float* Ap = (gk < K) ? (A0 + (size_t)grow * K + gk)
                                           : (A1 + (size_t)grow * K + (gk - K));
                av = *(const float4*)Ap;
            }
            As[ac + 0][ar] = av.x;
            As[ac + 1][ar] = av.y;
            As[ac + 2][ar] = av.z;
            As[ac + 3][ar] = av.w;
        }
        {
            int gk = kk + br;
            const float* Bp = (gk < K) ? (B0 + (size_t)gk * N + blockCol + bc)
                                       : (B1 + (size_t)(gk - K) * N + blockCol + bc);
            float4 bv = *(const float4*)Bp;
            Bs[br][bc + 0] = bv.x;
            Bs[br][bc + 1] = bv.y;
            Bs[br][bc + 2] = bv.z;
            Bs[br][bc + 3] = bv.w;
        }
        __syncthreads();
#pragma unroll
        for (int k = 0; k < BK; k++) {
            float a[4], b[4];
#pragma unroll
            for (int i = 0; i < 4; i++) a[i] = As[k][ty * 4 + i];
#pragma unroll
            for (int j = 0; j < 4; j++) b[j] = Bs[k][tx * 4 + j];
#pragma unroll
            for (int i = 0; i < 4; i++)
#pragma unroll
                for (int j = 0; j < 4; j++) c[i][j] += a[i] * b[j];
        }
        __syncthreads();
    }

    int row0 = blockRow + ty * 4;
    int col0 = blockCol + tx * 4;
#pragma unroll
    for (int i = 0; i < 4; i++) {
        int r = row0 + i;
        if (r < M) {
#pragma unroll
            for (int j = 0; j < 4; j++) {
                float v = c[i][j] + bias[col0 + j];
                if (do_relu) v = fmaxf(v, 0.f);
                out[(size_t)r * N + col0 + j] = v;
            }
        }
    }
}

// ---------------- log_softmax over 64 cols: one warp per row ----------------
__global__ void k_lsm(float* __restrict__ out) {
    int gw   = (blockIdx.x * blockDim.x + threadIdx.x) >> 5;
    int lane = threadIdx.x & 31;
    if (gw >= NN) return;
    const float* row = g_h3 + (size_t)gw * 64;
    float v0 = row[lane];
    float v1 = row[lane + 32];
    float m = fmaxf(v0, v1);
#pragma unroll
    for (int off = 16; off; off >>= 1) m = fmaxf(m, __shfl_xor_sync(0xffffffffu, m, off));
    float s = __expf(v0 - m) + __expf(v1 - m);
#pragma unroll
    for (int off = 16; off; off >>= 1) s += __shfl_xor_sync(0xffffffffu, s, off);
    float lse = m + __logf(s);
    float* o = out + (size_t)gw * 64;
    o[lane]      = v0 - lse;
    o[lane + 32] = v1 - lse;
}

// ---------------- launch ----------------
extern "C" void kernel_launch(void* const* d_in, const int* in_sizes, int n_in,
                              void* d_out, int out_size) {
    const float* x   = (const float*)d_in[0];
    const int*   ei  = (const int*)d_in[1];   // int32 per metadata (JAX x64 off); probed at runtime
    const float* W1l = (const float*)d_in[2];
    const float* W1r = (const float*)d_in[3];
    const float* b1  = (const float*)d_in[4];
    const float* W2l = (const float*)d_in[5];
    const float* W2r = (const float*)d_in[6];
    const float* b2  = (const float*)d_in[7];
    const float* W3l = (const float*)d_in[8];
    const float* W3r = (const float*)d_in[9];
    const float* b3  = (const float*)d_in[10];
    float* out = (float*)d_out;

    int E = in_sizes[1] / 2;

    // dtype probe + CSR build
    k_detect<<<1, 32>>>(ei);
    k_zero_counts<<<(NN + 255) / 256, 256>>>();
    k_count<<<(E + 255) / 256, 256>>>(ei, E);
    k_scan<<<1, 1024>>>(NN);
    k_fill<<<(E + 255) / 256, 256>>>(ei, E);

    int aggBlocks = (NN * 32 + 255) / 256;
    dim3 gemmBlk(256);

    // Layer 1: C=128 -> 256
    k_agg<128><<<aggBlocks, 256>>>(x, -1);
    {
        dim3 grid((NN + 63) / 64, 256 / 64);
        k_gemm<<<grid, gemmBlk>>>(x, -1, W1l, W1r, b1, /*out=*/1, NN, 256, 128, 1);
    }
    // Layer 2: C=256 -> 128
    k_agg<256><<<aggBlocks, 256>>>(nullptr, 1);
    {
        dim3 grid((NN + 63) / 64, 128 / 64);
        k_gemm<<<grid, gemmBlk>>>(nullptr, 1, W2l, W2r, b2, /*out=*/2, NN, 128, 256, 1);
    }
    // Layer 3: C=128 -> 64
    k_agg<128><<<aggBlocks, 256>>>(nullptr, 2);
    {
        dim3 grid((NN + 63) / 64, 64 / 64);
        k_gemm<<<grid, gemmBlk>>>(nullptr, 2, W3l, W3r, b3, /*out=*/3, NN, 64, 128, 0);
    }
    // log_softmax
    k_lsm<<<aggBlocks, 256>>>(out);
}

// round 4
// speedup vs baseline: 1.6535x; 1.6535x over previous
#include <cuda_runtime.h>
#include <math.h>

#define NN 100000
#define EE 600000
#define NB_SCAN ((NN + 255) / 256)   // 391

// ---------------- static scratch (no allocations allowed) ----------------
__device__ int   g_is64;
__device__ int   g_deg[NN];
__device__ int   g_cur[NN];
__device__ int   g_rowstart[NN + 1];
__device__ int   g_col[EE];
__device__ int   g_part[512];
__device__ int   g_partpre[512];
__device__ float g_mean[(size_t)NN * 256];
__device__ float g_h1[(size_t)NN * 256];
__device__ float g_h2[(size_t)NN * 128];
__device__ float g_h3[(size_t)NN * 64];

__device__ __forceinline__ float* devbuf(int id) {
    switch (id) {
        case 0: return g_mean;
        case 1: return g_h1;
        case 2: return g_h2;
        default: return g_h3;
    }
}

// ---------------- dtype probe: int32 vs int64 edge_index ----------------
__global__ void k_detect(const int* __restrict__ w) {
    if (threadIdx.x == 0 && blockIdx.x == 0) {
        int is64 = 1;
        for (int i = 0; i < 64; i++) {
            if (w[2 * i + 1] != 0) { is64 = 0; break; }
        }
        g_is64 = is64;
    }
}

__device__ __forceinline__ int edge_src(const int* w, int E, int e) {
    return g_is64 ? w[2 * e] : w[e];
}
__device__ __forceinline__ int edge_dst(const int* w, int E, int e) {
    return g_is64 ? w[2 * (E + e)] : w[E + e];
}

// ---------------- CSR build ----------------
__global__ void k_zero_counts() {
    int i = blockIdx.x * blockDim.x + threadIdx.x;
    if (i < NN) { g_deg[i] = 0; g_cur[i] = 0; }
}

__global__ void k_count(const int* __restrict__ w, int E) {
    int e = blockIdx.x * blockDim.x + threadIdx.x;
    if (e < E) atomicAdd(&g_deg[edge_dst(w, E, e)], 1);
}

// ---- parallel scan: phase 1, per-block sums ----
__global__ void k_part_sum() {
    __shared__ int sm[8];
    int i = blockIdx.x * 256 + threadIdx.x;
    int v = (i < NN) ? g_deg[i] : 0;
#pragma unroll
    for (int off = 16; off; off >>= 1) v += __shfl_xor_sync(0xffffffffu, v, off);
    if ((threadIdx.x & 31) == 0) sm[threadIdx.x >> 5] = v;
    __syncthreads();
    if (threadIdx.x == 0) {
        int s = 0;
#pragma unroll
        for (int k = 0; k < 8; k++) s += sm[k];
        g_part[blockIdx.x] = s;
    }
}

// ---- phase 2: scan the 391 partials (one small block) ----
__global__ void k_part_scan() {
    __shared__ int buf[512];
    int t = threadIdx.x;
    buf[t] = (t < NB_SCAN) ? g_part[t] : 0;
    __syncthreads();
    for (int off = 1; off < 512; off <<= 1) {
        int v = (t >= off) ? buf[t - off] : 0;
        __syncthreads();
        buf[t] += v;
        __syncthreads();
    }
    if (t < NB_SCAN) g_partpre[t] = buf[t] - g_part[t];  // exclusive
}

// ---- phase 3: local scan + scatter rowstarts ----
__global__ void k_row_write(int E) {
    __shared__ int buf[256];
    int t = threadIdx.x;
    int i = blockIdx.x * 256 + t;
    int d = (i < NN) ? g_deg[i] : 0;
    buf[t] = d;
    __syncthreads();
    for (int off = 1; off < 256; off <<= 1) {
        int v = (t >= off) ? buf[t - off] : 0;
        __syncthreads();
        buf[t] += v;
        __syncthreads();
    }
    if (i < NN) {
        g_rowstart[i] = g_partpre[blockIdx.x] + buf[t] - d;
        if (i == NN - 1) g_rowstart[NN] = E;
    }
}

__global__ void k_fill(const int* __restrict__ w, int E) {
    int e = blockIdx.x * blockDim.x + threadIdx.x;
    if (e < E) {
        int src = edge_src(w, E, e);
        int dst = edge_dst(w, E, e);
        int pos = g_rowstart[dst] + atomicAdd(&g_cur[dst], 1);
        g_col[pos] = src;
    }
}

// ---------------- mean aggregation: one warp per node ----------------
template <int C>
__global__ void k_agg(const float* __restrict__ ext, int src_id) {
    const float* feat = ext ? ext : devbuf(src_id);
    int gw   = (blockIdx.x * blockDim.x + threadIdx.x) >> 5;
    int lane = threadIdx.x & 31;
    if (gw >= NN) return;
    int s = g_rowstart[gw];
    int e = g_rowstart[gw + 1];
    constexpr int V = C / 128;
    float4 acc[V];
#pragma unroll
    for (int v = 0; v < V; v++) acc[v] = make_float4(0.f, 0.f, 0.f, 0.f);
    for (int i = s; i < e; i++) {
        int nb = g_col[i];
        const float4* row = (const float4*)(feat + (size_t)nb * C);
#pragma unroll
        for (int v = 0; v < V; v++) {
            float4 r = row[lane + 32 * v];
            acc[v].x += r.x; acc[v].y += r.y; acc[v].z += r.z; acc[v].w += r.w;
        }
    }
    float inv = 1.0f / (float)max(e - s, 1);
    float4* o = (float4*)(g_mean + (size_t)gw * C);
#pragma unroll
    for (int v = 0; v < V; v++) {
        float4 r;
        r.x = acc[v].x * inv; r.y = acc[v].y * inv;
        r.z = acc[v].z * inv; r.w = acc[v].w * inv;
        o[lane + 32 * v] = r;
    }
}

// ---------------- tf32 tensor-core fused dual GEMM ----------------
// out[M,N] = [g_mean | A1] @ [B0 ; B1] + bias (+relu)
// BM=128, BN=64, BK=32; 256 threads = 8 warps in 4(M) x 2(N); warp tile 32x32.
__device__ __forceinline__ float f2tf32(float x) {
    unsigned u;
    asm("cvt.rna.tf32.f32 %0, %1;" : "=r"(u) : "f"(x));
    return __uint_as_float(u);
}

__global__ void __launch_bounds__(256)
k_gemm_tc(const float* __restrict__ A1ext, int a1_id,
          const float* __restrict__ B0, const float* __restrict__ B1,
          const float* __restrict__ bias, int out_id,
          int M, int N, int K, int do_relu) {
    const float* A0 = g_mean;
    const float* A1 = A1ext ? A1ext : devbuf(a1_id);
    float* out = devbuf(out_id);

    constexpr int BM = 128, BN = 64, BK = 32;
    __shared__ float As[BK][BM + 4];   // k-major
    __shared__ float Bs[BK][BN + 4];

    const int tid  = threadIdx.x;
    const int lane = tid & 31;
    const int warp = tid >> 5;
    const int wm   = warp & 3;   // 0..3 -> 32-row slab
    const int wn   = warp >> 2;  // 0..1 -> 32-col slab
    const int gid  = lane >> 2;  // 0..7
    const int tig  = lane & 3;   // 0..3

    const int blockRow = blockIdx.x * BM;
    const int blockCol = blockIdx.y * BN;

    float c[2][4][4];
#pragma unroll
    for (int mt = 0; mt < 2; mt++)
#pragma unroll
        for (int nt = 0; nt < 4; nt++)
#pragma unroll
            for (int r = 0; r < 4; r++) c[mt][nt][r] = 0.f;

    const int K2 = 2 * K;
    const int T  = K2 / BK;

    // global-load index mapping (fully coalesced)
    const int a_r0  = (4 * tid) >> 3;          // row of first A float4
    const int a_c40 = (4 * tid) & 7;           // float4-col of first A f4
    const int b_k0  = (2 * tid) >> 4;          // k-row of first B float4
    const int b_c40 = (2 * tid) & 15;

    float4 pa[4], pb[2];

    // prefetch tile 0
    {
        const float* Ab = (0 < K) ? A0 : A1;   // kk=0 always < K
#pragma unroll
        for (int j = 0; j < 4; j++) {
            int f = 4 * tid + j;
            int r = f >> 3, c4 = f & 7;
            int grow = blockRow + r;
            pa[j] = (grow < M) ? *(const float4*)(Ab + (size_t)grow * K + c4 * 4)
                               : make_float4(0.f, 0.f, 0.f, 0.f);
        }
#pragma unroll
        for (int j = 0; j < 2; j++) {
            int f = 2 * tid + j;
            int kr = f >> 4, c4 = f & 15;
            pb[j] = *(const float4*)(B0 + (size_t)kr * N + blockCol + c4 * 4);
        }
    }

    for (int t = 0; t < T; t++) {
        // store prefetched tile to smem (convert to tf32)
#pragma unroll
        for (int j = 0; j < 4; j++) {
            int f = 4 * tid + j;
            int r = f >> 3, c4 = f & 7;
            As[c4 * 4 + 0][r] = f2tf32(pa[j].x);
            As[c4 * 4 + 1][r] = f2tf32(pa[j].y);
            As[c4 * 4 + 2][r] = f2tf32(pa[j].z);
            As[c4 * 4 + 3][r] = f2tf32(pa[j].w);
        }
#pragma unroll
        for (int j = 0; j < 2; j++) {
            int f = 2 * tid + j;
            int kr = f >> 4, c4 = f & 15;
            float4 v;
            v.x = f2tf32(pb[j].x); v.y = f2tf32(pb[j].y);
            v.z = f2tf32(pb[j].z); v.w = f2tf32(pb[j].w);
            *(float4*)&Bs[kr][c4 * 4] = v;
        }
        __syncthreads();

        // prefetch next tile (overlaps with MMA below)
        if (t + 1 < T) {
            int kk = (t + 1) * BK;
            const float* Ab = (kk < K) ? (A0 + kk) : (A1 + (kk - K));
            const float* Bb = (kk < K) ? (B0 + (size_t)kk * N) : (B1 + (size_t)(kk - K) * N);
#pragma unroll
            for (int j = 0; j < 4; j++) {
                int f = 4 * tid + j;
                int r = f >> 3, c4 = f & 7;
                int grow = blockRow + r;
                pa[j] = (grow < M) ? *(const float4*)(Ab + (size_t)grow * K + c4 * 4)
                                   : make_float4(0.f, 0.f, 0.f, 0.f);
            }
#pragma unroll
            for (int j = 0; j < 2; j++) {
                int f = 2 * tid + j;
                int kr = f >> 4, c4 = f & 15;
                pb[j] = *(const float4*)(Bb + (size_t)kr * N + blockCol + c4 * 4);
            }
        }

        // compute: 4 k-steps of 8
#pragma unroll
        for (int kb = 0; kb < BK; kb += 8) {
            unsigned af[2][4], bf[4][2];
#pragma unroll
            for (int mt = 0; mt < 2; mt++) {
                int rb = wm * 32 + mt * 16 + gid;
                af[mt][0] = __float_as_uint(As[kb + tig][rb]);
                af[mt][1] = __float_as_uint(As[kb + tig][rb + 8]);
                af[mt][2] = __float_as_uint(As[kb + tig + 4][rb]);
                af[mt][3] = __float_as_uint(As[kb + tig + 4][rb + 8]);
            }
#pragma unroll
            for (int nt = 0; nt < 4; nt++) {
                int cb = wn * 32 + nt * 8 + gid;
                bf[nt][0] = __float_as_uint(Bs[kb + tig][cb]);
                bf[nt][1] = __float_as_uint(Bs[kb + tig + 4][cb]);
            }
#pragma unroll
            for (int mt = 0; mt < 2; mt++)
#pragma unroll
                for (int nt = 0; nt < 4; nt++) {
                    asm volatile(
                        "mma.sync.aligned.m16n8k8.row.col.f32.tf32.tf32.f32 "
                        "{%0,%1,%2,%3}, {%4,%5,%6,%7}, {%8,%9}, {%0,%1,%2,%3};\n"
                        : "+f"(c[mt][nt][0]), "+f"(c[mt][nt][1]),
                          "+f"(c[mt][nt][2]), "+f"(c[mt][nt][3])
                        : "r"(af[mt][0]), "r"(af[mt][1]), "r"(af[mt][2]), "r"(af[mt][3]),
                          "r"(bf[nt][0]), "r"(bf[nt][1]));
                }
        }
        __syncthreads();
    }

    // epilogue: bias + relu + store
#pragma unroll
    for (int nt = 0; nt < 4; nt++) {
        int col = blockCol + wn * 32 + nt * 8 + 2 * tig;
        float bv0 = bias[col];
        float bv1 = bias[col + 1];
#pragma unroll
        for (int mt = 0; mt < 2; mt++) {
            int row = blockRow + wm * 32 + mt * 16 + gid;
#pragma unroll
            for (int h = 0; h < 2; h++) {   // row, row+8
                int r = row + h * 8;
                if (r < M) {
                    float v0 = c[mt][nt][2 * h + 0] + bv0;
                    float v1 = c[mt][nt][2 * h + 1] + bv1;
                    if (do_relu) { v0 = fmaxf(v0, 0.f); v1 = fmaxf(v1, 0.f); }
                    out[(size_t)r * N + col]     = v0;
                    out[(size_t)r * N + col + 1] = v1;
                }
            }
        }
    }
}

// ---------------- log_softmax over 64 cols: one warp per row ----------------
__global__ void k_lsm(float* __restrict__ out) {
    int gw   = (blockIdx.x * blockDim.x + threadIdx.x) >> 5;
    int lane = threadIdx.x & 31;
    if (gw >= NN) return;
    const float* row = g_h3 + (size_t)gw * 64;
    float v0 = row[lane];
    float v1 = row[lane + 32];
    float m = fmaxf(v0, v1);
#pragma unroll
    for (int off = 16; off; off >>= 1) m = fmaxf(m, __shfl_xor_sync(0xffffffffu, m, off));
    float s = __expf(v0 - m) + __expf(v1 - m);
#pragma unroll
    for (int off = 16; off; off >>= 1) s += __shfl_xor_sync(0xffffffffu, s, off);
    float lse = m + __logf(s);
    float* o = out + (size_t)gw * 64;
    o[lane]      = v0 - lse;
    o[lane + 32] = v1 - lse;
}

// ---------------- launch ----------------
extern "C" void kernel_launch(void* const* d_in, const int* in_sizes, int n_in,
                              void* d_out, int out_size) {
    const float* x   = (const float*)d_in[0];
    const int*   ei  = (const int*)d_in[1];
    const float* W1l = (const float*)d_in[2];
    const float* W1r = (const float*)d_in[3];
    const float* b1  = (const float*)d_in[4];
    const float* W2l = (const float*)d_in[5];
    const float* W2r = (const float*)d_in[6];
    const float* b2  = (const float*)d_in[7];
    const float* W3l = (const float*)d_in[8];
    const float* W3r = (const float*)d_in[9];
    const float* b3  = (const float*)d_in[10];
    float* out = (float*)d_out;

    int E = in_sizes[1] / 2;

    // dtype probe + CSR build (parallel scan)
    k_detect<<<1, 32>>>(ei);
    k_zero_counts<<<(NN + 255) / 256, 256>>>();
    k_count<<<(E + 255) / 256, 256>>>(ei, E);
    k_part_sum<<<NB_SCAN, 256>>>();
    k_part_scan<<<1, 512>>>();
    k_row_write<<<NB_SCAN, 256>>>(E);
    k_fill<<<(E + 255) / 256, 256>>>(ei, E);

    int aggBlocks = (NN * 32 + 255) / 256;

    // Layer 1: C=128 -> 256
    k_agg<128><<<aggBlocks, 256>>>(x, -1);
    {
        dim3 grid((NN + 127) / 128, 256 / 64);
        k_gemm_tc<<<grid, 256>>>(x, -1, W1l, W1r, b1, /*out=*/1, NN, 256, 128, 1);
    }
    // Layer 2: C=256 -> 128
    k_agg<256><<<aggBlocks, 256>>>(nullptr, 1);
    {
        dim3 grid((NN + 127) / 128, 128 / 64);
        k_gemm_tc<<<grid, 256>>>(nullptr, 1, W2l, W2r, b2, /*out=*/2, NN, 128, 256, 1);
    }
    // Layer 3: C=128 -> 64
    k_agg<128><<<aggBlocks, 256>>>(nullptr, 2);
    {
        dim3 grid((NN + 127) / 128, 64 / 64);
        k_gemm_tc<<<grid, 256>>>(nullptr, 2, W3l, W3r, b3, /*out=*/3, NN, 64, 128, 0);
    }
    // log_softmax
    k_lsm<<<aggBlocks, 256>>>(out);
}

// round 6
// speedup vs baseline: 2.9166x; 1.7639x over previous
#include <cuda_runtime.h>
#include <cuda_bf16.h>
#include <math.h>

#define NN 100000
#define EE 600000
#define NB_SCAN ((NN + 255) / 256)   // 391

// ---------------- static scratch (no allocations allowed) ----------------
__device__ int   g_is64;
__device__ int   g_deg[NN];
__device__ int   g_cur[NN];
__device__ int   g_rowstart[NN + 1];
__device__ int   g_col[EE];
__device__ int   g_part[512];
__device__ int   g_partpre[512];

__device__ __nv_bfloat16 g_xb[(size_t)NN * 128];
__device__ __nv_bfloat16 g_meanb[(size_t)NN * 128];
__device__ __nv_bfloat16 g_h1b[(size_t)NN * 256];
__device__ __nv_bfloat16 g_h2b[(size_t)NN * 128];
__device__ float         g_t[(size_t)NN * 256];     // fp32 GEMM out (L2: 256 cols, L3: 128 cols)
__device__ __nv_bfloat16 g_wt1[256 * 256];
__device__ __nv_bfloat16 g_wt2[256 * 256];
__device__ __nv_bfloat16 g_wt3[128 * 128];

__device__ __forceinline__ __nv_bfloat16* bbuf(int id) {
    switch (id) {
        case 0: return g_xb;
        case 1: return g_meanb;
        case 2: return g_h1b;
        case 3: return g_h2b;
        case 4: return g_wt1;
        case 5: return g_wt2;
        default: return g_wt3;
    }
}

// ---------------- dtype probe: int32 vs int64 edge_index ----------------
__global__ void k_detect(const int* __restrict__ w) {
    if (threadIdx.x == 0 && blockIdx.x == 0) {
        int is64 = 1;
        for (int i = 0; i < 64; i++) {
            if (w[2 * i + 1] != 0) { is64 = 0; break; }
        }
        g_is64 = is64;
    }
}
__device__ __forceinline__ int edge_src(const int* w, int E, int e) {
    return g_is64 ? w[2 * e] : w[e];
}
__device__ __forceinline__ int edge_dst(const int* w, int E, int e) {
    return g_is64 ? w[2 * (E + e)] : w[E + e];
}

// ---------------- CSR build ----------------
__global__ void k_zero_counts() {
    int i = blockIdx.x * blockDim.x + threadIdx.x;
    if (i < NN) { g_deg[i] = 0; g_cur[i] = 0; }
}
__global__ void k_count(const int* __restrict__ w, int E) {
    int e = blockIdx.x * blockDim.x + threadIdx.x;
    if (e < E) atomicAdd(&g_deg[edge_dst(w, E, e)], 1);
}
__global__ void k_part_sum() {
    __shared__ int sm[8];
    int i = blockIdx.x * 256 + threadIdx.x;
    int v = (i < NN) ? g_deg[i] : 0;
#pragma unroll
    for (int off = 16; off; off >>= 1) v += __shfl_xor_sync(0xffffffffu, v, off);
    if ((threadIdx.x & 31) == 0) sm[threadIdx.x >> 5] = v;
    __syncthreads();
    if (threadIdx.x == 0) {
        int s = 0;
#pragma unroll
        for (int k = 0; k < 8; k++) s += sm[k];
        g_part[blockIdx.x] = s;
    }
}
__global__ void k_part_scan() {
    __shared__ int buf[512];
    int t = threadIdx.x;
    buf[t] = (t < NB_SCAN) ? g_part[t] : 0;
    __syncthreads();
    for (int off = 1; off < 512; off <<= 1) {
        int v = (t >= off) ? buf[t - off] : 0;
        __syncthreads();
        buf[t] += v;
        __syncthreads();
    }
    if (t < NB_SCAN) g_partpre[t] = buf[t] - g_part[t];
}
__global__ void k_row_write(int E) {
    __shared__ int buf[256];
    int t = threadIdx.x;
    int i = blockIdx.x * 256 + t;
    int d = (i < NN) ? g_deg[i] : 0;
    buf[t] = d;
    __syncthreads();
    for (int off = 1; off < 256; off <<= 1) {
        int v = (t >= off) ? buf[t - off] : 0;
        __syncthreads();
        buf[t] += v;
        __syncthreads();
    }
    if (i < NN) {
        g_rowstart[i] = g_partpre[blockIdx.x] + buf[t] - d;
        if (i == NN - 1) g_rowstart[NN] = E;
    }
}
__global__ void k_fill(const int* __restrict__ w, int E) {
    int e = blockIdx.x * blockDim.x + threadIdx.x;
    if (e < E) {
        int src = edge_src(w, E, e);
        int dst = edge_dst(w, E, e);
        int pos = g_rowstart[dst] + atomicAdd(&g_cur[dst], 1);
        g_col[pos] = src;
    }
}

// ---------------- conversions ----------------
__global__ void k_cvt_x(const float* __restrict__ x) {
    size_t i = (size_t)blockIdx.x * blockDim.x + threadIdx.x;
    if (i < (size_t)NN * 128) g_xb[i] = __float2bfloat16(x[i]);
}
// Build transposed bf16 weight: dst[n*K2 + k].
// stackK=1: k<K2/2 -> Wl[k*N+n], else Wr[(k-K2/2)*N+n]   (N = full out width)
// stackK=0: n<N/2 -> Wl[k*(N/2)+n], else Wr[k*(N/2)+(n-N/2)]
__global__ void k_cvtw(const float* __restrict__ Wl, const float* __restrict__ Wr,
                       int dst_id, int K2, int N, int stackK) {
    int idx = blockIdx.x * blockDim.x + threadIdx.x;
    if (idx >= N * K2) return;
    int n = idx / K2, k = idx % K2;
    float v;
    if (stackK) {
        int half = K2 / 2;
        v = (k < half) ? Wl[(size_t)k * N + n] : Wr[(size_t)(k - half) * N + n];
    } else {
        int half = N / 2;
        v = (n < half) ? Wl[(size_t)k * half + n] : Wr[(size_t)k * half + (n - half)];
    }
    bbuf(dst_id)[(size_t)n * K2 + k] = __float2bfloat16(v);
}

// ---------------- L1 pre-aggregation: mean of bf16 x rows -> bf16 mean ----------------
__global__ void k_agg_pre() {
    int gw   = (blockIdx.x * blockDim.x + threadIdx.x) >> 5;
    int lane = threadIdx.x & 31;
    if (gw >= NN) return;
    int s = g_rowstart[gw], e = g_rowstart[gw + 1];
    float4 acc = make_float4(0.f, 0.f, 0.f, 0.f);
    for (int i = s; i < e; i++) {
        int nb = g_col[i];
        uint2 v = *(const uint2*)(g_xb + (size_t)nb * 128 + lane * 4);
        __nv_bfloat162 p0 = *reinterpret_cast<__nv_bfloat162*>(&v.x);
        __nv_bfloat162 p1 = *reinterpret_cast<__nv_bfloat162*>(&v.y);
        float2 f0 = __bfloat1622float2(p0);
        float2 f1 = __bfloat1622float2(p1);
        acc.x += f0.x; acc.y += f0.y; acc.z += f1.x; acc.w += f1.y;
    }
    float inv = 1.0f / (float)max(e - s, 1);
    __nv_bfloat162 o0, o1;
    o0.x = __float2bfloat16(acc.x * inv); o0.y = __float2bfloat16(acc.y * inv);
    o1.x = __float2bfloat16(acc.z * inv); o1.y = __float2bfloat16(acc.w * inv);
    uint2 ov;
    ov.x = *reinterpret_cast<unsigned*>(&o0);
    ov.y = *reinterpret_cast<unsigned*>(&o1);
    *(uint2*)(g_meanb + (size_t)gw * 128 + lane * 4) = ov;
}

// ---------------- bf16 tensor-core GEMM ----------------
// out[M,N] = [A0 | A1] @ Bt^T (+bias)(+relu), A k-split at Ka.
// Bt is [N, K2] (transposed weights, bf16). BM=128 BN=64 BK=32, 8 warps.
#define SA 40   // smem row stride in halves (80B, 16B-aligned, conflict-free)

__global__ void __launch_bounds__(256)
k_gemm_bf16(int a0_id, int a1_id, int Ka, int b_id,
            const float* __restrict__ bias,
            int outb_id,          // >=0: bf16 out buffer id; <0: fp32 out g_t
            int M, int N, int K2, int do_relu) {
    const __nv_bfloat16* A0 = bbuf(a0_id);
    const __nv_bfloat16* A1 = bbuf(a1_id);
    const __nv_bfloat16* Bt = bbuf(b_id);
    const int sA0 = Ka, sA1 = K2 - Ka;

    constexpr int BM = 128, BN = 64, BK = 32;
    __shared__ __nv_bfloat16 As[BM * SA];
    __shared__ __nv_bfloat16 Bs[BN * SA];

    const int tid  = threadIdx.x;
    const int lane = tid & 31;
    const int warp = tid >> 5;
    const int wm   = warp & 3;
    const int wn   = warp >> 2;
    const int gid  = lane >> 2;
    const int tig  = lane & 3;

    const int blockRow = blockIdx.x * BM;
    const int blockCol = blockIdx.y * BN;

    float c[2][4][4];
#pragma unroll
    for (int mt = 0; mt < 2; mt++)
#pragma unroll
        for (int nt = 0; nt < 4; nt++)
#pragma unroll
            for (int r = 0; r < 4; r++) c[mt][nt][r] = 0.f;

    const int T = K2 / BK;
    uint4 pa[2], pb;

    // prefetch tile 0
    {
        const int kk = 0;
#pragma unroll
        for (int j = 0; j < 2; j++) {
            int f = tid * 2 + j;
            int r = f >> 2, c16 = f & 3;
            int grow = blockRow + r;
            int gk = kk + c16 * 8;
            if (grow < M) {
                const __nv_bfloat16* p = (gk < Ka) ? (A0 + (size_t)grow * sA0 + gk)
                                                   : (A1 + (size_t)grow * sA1 + (gk - Ka));
                pa[j] = *(const uint4*)p;
            } else pa[j] = make_uint4(0, 0, 0, 0);
        }
        {
            int r = tid >> 2, c16 = tid & 3;
            pb = *(const uint4*)(Bt + (size_t)(blockCol + r) * K2 + kk + c16 * 8);
        }
    }

    for (int t = 0; t < T; t++) {
#pragma unroll
        for (int j = 0; j < 2; j++) {
            int f = tid * 2 + j;
            int r = f >> 2, c16 = f & 3;
            *(uint4*)(As + r * SA + c16 * 8) = pa[j];
        }
        {
            int r = tid >> 2, c16 = tid & 3;
            *(uint4*)(Bs + r * SA + c16 * 8) = pb;
        }
        __syncthreads();

        if (t + 1 < T) {
            const int kk = (t + 1) * BK;
#pragma unroll
            for (int j = 0; j < 2; j++) {
                int f = tid * 2 + j;
                int r = f >> 2, c16 = f & 3;
                int grow = blockRow + r;
                int gk = kk + c16 * 8;
                if (grow < M) {
                    const __nv_bfloat16* p = (gk < Ka) ? (A0 + (size_t)grow * sA0 + gk)
                                                       : (A1 + (size_t)grow * sA1 + (gk - Ka));
                    pa[j] = *(const uint4*)p;
                } else pa[j] = make_uint4(0, 0, 0, 0);
            }
            {
                int r = tid >> 2, c16 = tid & 3;
                pb = *(const uint4*)(Bt + (size_t)(blockCol + r) * K2 + kk + c16 * 8);
            }
        }

#pragma unroll
        for (int ks = 0; ks < BK; ks += 16) {
            unsigned af[2][4], bf[4][2];
#pragma unroll
            for (int mt = 0; mt < 2; mt++) {
                int rb = wm * 32 + mt * 16 + gid;
                af[mt][0] = *(const unsigned*)(As + rb * SA + ks + 2 * tig);
                af[mt][1] = *(const unsigned*)(As + (rb + 8) * SA + ks + 2 * tig);
                af[mt][2] = *(const unsigned*)(As + rb * SA + ks + 2 * tig + 8);
                af[mt][3] = *(const unsigned*)(As + (rb + 8) * SA + ks + 2 * tig + 8);
            }
#pragma unroll
            for (int nt = 0; nt < 4; nt++) {
                int nb = wn * 32 + nt * 8 + gid;
                bf[nt][0] = *(const unsigned*)(Bs + nb * SA + ks + 2 * tig);
                bf[nt][1] = *(const unsigned*)(Bs + nb * SA + ks + 2 * tig + 8);
            }
#pragma unroll
            for (int mt = 0; mt < 2; mt++)
#pragma unroll
                for (int nt = 0; nt < 4; nt++) {
                    asm volatile(
                        "mma.sync.aligned.m16n8k16.row.col.f32.bf16.bf16.f32 "
                        "{%0,%1,%2,%3}, {%4,%5,%6,%7}, {%8,%9}, {%0,%1,%2,%3};\n"
                        : "+f"(c[mt][nt][0]), "+f"(c[mt][nt][1]),
                          "+f"(c[mt][nt][2]), "+f"(c[mt][nt][3])
                        : "r"(af[mt][0]), "r"(af[mt][1]), "r"(af[mt][2]), "r"(af[mt][3]),
                          "r"(bf[nt][0]), "r"(bf[nt][1]));
                }
        }
        __syncthreads();
    }

    // epilogue
    __nv_bfloat16* outb = (outb_id >= 0) ? bbuf(outb_id) : nullptr;
#pragma unroll
    for (int nt = 0; nt < 4; nt++) {
        int col = blockCol + wn * 32 + nt * 8 + 2 * tig;
        float bv0 = bias ? bias[col] : 0.f;
        float bv1 = bias ? bias[col + 1] : 0.f;
#pragma unroll
        for (int mt = 0; mt < 2; mt++) {
#pragma unroll
            for (int h = 0; h < 2; h++) {
                int r = blockRow + wm * 32 + mt * 16 + gid + h * 8;
                if (r < M) {
                    float v0 = c[mt][nt][2 * h + 0] + bv0;
                    float v1 = c[mt][nt][2 * h + 1] + bv1;
                    if (do_relu) { v0 = fmaxf(v0, 0.f); v1 = fmaxf(v1, 0.f); }
                    if (outb) {
                        __nv_bfloat162 o;
                        o.x = __float2bfloat16(v0);
                        o.y = __float2bfloat16(v1);
                        *(unsigned*)(outb + (size_t)r * N + col) =
                            *reinterpret_cast<unsigned*>(&o);
                    } else {
                        float2 o = make_float2(v0, v1);
                        *(float2*)(g_t + (size_t)r * N + col) = o;
                    }
                }
            }
        }
    }
}

// ---------------- agg-combine: h = act(mean_nb(t[:, :C]) + t[i, C:] + bias) ----------------
// MODE 0: relu -> bf16 g_h2b (C=128, t stride 256)
// MODE 1: log_softmax -> fp32 out (C=64, t stride 128)
template <int C, int MODE>
__global__ void k_agg_combine(const float* __restrict__ bias, float* __restrict__ out) {
    int gw   = (blockIdx.x * blockDim.x + threadIdx.x) >> 5;
    int lane = threadIdx.x & 31;
    if (gw >= NN) return;
    int s = g_rowstart[gw], e = g_rowstart[gw + 1];
    constexpr int TC = 2 * C;

    if (MODE == 0) {
        float4 acc = make_float4(0.f, 0.f, 0.f, 0.f);
        for (int i = s; i < e; i++) {
            int nb = g_col[i];
            float4 v = *(const float4*)(g_t + (size_t)nb * TC + lane * 4);
            acc.x += v.x; acc.y += v.y; acc.z += v.z; acc.w += v.w;
        }
        float inv = 1.0f / (float)max(e - s, 1);
        float4 sv = *(const float4*)(g_t + (size_t)gw * TC + C + lane * 4);
        float4 bv = *(const float4*)(bias + lane * 4);
        float v0 = fmaxf(acc.x * inv + sv.x + bv.x, 0.f);
        float v1 = fmaxf(acc.y * inv + sv.y + bv.y, 0.f);
        float v2 = fmaxf(acc.z * inv + sv.z + bv.z, 0.f);
        float v3 = fmaxf(acc.w * inv + sv.w + bv.w, 0.f);
        __nv_bfloat162 o0, o1;
        o0.x = __float2bfloat16(v0); o0.y = __float2bfloat16(v1);
        o1.x = __float2bfloat16(v2); o1.y = __float2bfloat16(v3);
        uint2 ov;
        ov.x = *reinterpret_cast<unsigned*>(&o0);
        ov.y = *reinterpret_cast<unsigned*>(&o1);
        *(uint2*)(g_h2b + (size_t)gw * C + lane * 4) = ov;
    } else {
        float2 acc = make_float2(0.f, 0.f);
        for (int i = s; i < e; i++) {
            int nb = g_col[i];
            float2 v = *(const float2*)(g_t + (size_t)nb * TC + lane * 2);
            acc.x += v.x; acc.y += v.y;
        }
        float inv = 1.0f / (float)max(e - s, 1);
        float2 sv = *(const float2*)(g_t + (size_t)gw * TC + C + lane * 2);
        float2 bv = *(const float2*)(bias + lane * 2);
        float v0 = acc.x * inv + sv.x + bv.x;
        float v1 = acc.y * inv + sv.y + bv.y;
        float m = fmaxf(v0, v1);
#pragma unroll
        for (int off = 16; off; off >>= 1) m = fmaxf(m, __shfl_xor_sync(0xffffffffu, m, off));
        float sum = __expf(v0 - m) + __expf(v1 - m);
#pragma unroll
        for (int off = 16; off; off >>= 1) sum += __shfl_xor_sync(0xffffffffu, sum, off);
        float lse = m + __logf(sum);
        float2 o = make_float2(v0 - lse, v1 - lse);
        *(float2*)(out + (size_t)gw * C + lane * 2) = o;
    }
}

// ---------------- launch ----------------
extern "C" void kernel_launch(void* const* d_in, const int* in_sizes, int n_in,
                              void* d_out, int out_size) {
    const float* x   = (const float*)d_in[0];
    const int*   ei  = (const int*)d_in[1];
    const float* W1l = (const float*)d_in[2];
    const float* W1r = (const float*)d_in[3];
    const float* b1  = (const float*)d_in[4];
    const float* W2l = (const float*)d_in[5];
    const float* W2r = (const float*)d_in[6];
    const float* b2  = (const float*)d_in[7];
    const float* W3l = (const float*)d_in[8];
    const float* W3r = (const float*)d_in[9];
    const float* b3  = (const float*)d_in[10];
    float* out = (float*)d_out;

    int E = in_sizes[1] / 2;

    // dtype probe + CSR build
    k_detect<<<1, 32>>>(ei);
    k_zero_counts<<<(NN + 255) / 256, 256>>>();
    k_count<<<(E + 255) / 256, 256>>>(ei, E);
    k_part_sum<<<NB_SCAN, 256>>>();
    k_part_scan<<<1, 512>>>();
    k_row_write<<<NB_SCAN, 256>>>(E);
    k_fill<<<(E + 255) / 256, 256>>>(ei, E);

    // conversions
    k_cvt_x<<<(NN * 128 + 255) / 256, 256>>>(x);
    k_cvtw<<<(256 * 256 + 255) / 256, 256>>>(W1l, W1r, 4, 256, 256, 1);
    k_cvtw<<<(256 * 256 + 255) / 256, 256>>>(W2l, W2r, 5, 256, 256, 0);
    k_cvtw<<<(128 * 128 + 255) / 256, 256>>>(W3l, W3r, 6, 128, 128, 0);

    int aggBlocks = (NN * 32 + 255) / 256;

    // Layer 1: pre-agg (bf16) + dual-A GEMM -> h1b (relu)
    k_agg_pre<<<aggBlocks, 256>>>();
    {
        dim3 grid((NN + 127) / 128, 256 / 64);
        k_gemm_bf16<<<grid, 256>>>(1, 0, 128, 4, b1, /*outb=*/2, NN, 256, 256, 1);
    }
    // Layer 2: GEMM h1b @ [W2l|W2r] -> t (fp32), then agg-combine(relu) -> h2b
    {
        dim3 grid((NN + 127) / 128, 256 / 64);
        k_gemm_bf16<<<grid, 256>>>(2, 2, 256, 5, nullptr, /*outb=*/-1, NN, 256, 256, 0);
    }
    k_agg_combine<128, 0><<<aggBlocks, 256>>>(b2, nullptr);
    // Layer 3: GEMM h2b @ [W3l|W3r] -> t (fp32), then agg-combine + log_softmax -> out
    {
        dim3 grid((NN + 127) / 128, 128 / 64);
        k_gemm_bf16<<<grid, 256>>>(3, 3, 128, 6, nullptr, /*outb=*/-1, NN, 128, 128, 0);
    }
    k_agg_combine<64, 1><<<aggBlocks, 256>>>(b3, out);
}

// round 8
// speedup vs baseline: 3.5123x; 1.2042x over previous
#include <cuda_runtime.h>
#include <cuda_bf16.h>
#include <math.h>

#define NN 100000
#define EE 600000
#define NB_SCAN ((NN + 255) / 256)   // 391

// ---------------- static scratch (no allocations allowed) ----------------
__device__ int   g_is64;
__device__ int   g_deg[NN];
__device__ int   g_cur[NN];
__device__ int   g_rowstart[NN + 1];
__device__ int   g_col[EE];
__device__ int   g_part[512];
__device__ int   g_partpre[512];

__device__ __nv_bfloat16 g_xb[(size_t)NN * 128];
__device__ __nv_bfloat16 g_meanb[(size_t)NN * 128];
__device__ __nv_bfloat16 g_h1b[(size_t)NN * 256];
__device__ __nv_bfloat16 g_h2b[(size_t)NN * 128];
__device__ float         g_t[(size_t)NN * 256];
__device__ __nv_bfloat16 g_wt1[256 * 256];
__device__ __nv_bfloat16 g_wt2[256 * 256];
__device__ __nv_bfloat16 g_wt3[128 * 128];

__device__ __forceinline__ __nv_bfloat16* bbuf(int id) {
    switch (id) {
        case 0: return g_xb;
        case 1: return g_meanb;
        case 2: return g_h1b;
        case 3: return g_h2b;
        case 4: return g_wt1;
        case 5: return g_wt2;
        default: return g_wt3;
    }
}

// ---------------- init: zero counts + dtype probe (fused) ----------------
__global__ void k_init(const int* __restrict__ w) {
    int i = blockIdx.x * blockDim.x + threadIdx.x;
    if (i < NN) { g_deg[i] = 0; g_cur[i] = 0; }
    if (i == 0) {
        int is64 = 1;
        for (int j = 0; j < 64; j++) {
            if (w[2 * j + 1] != 0) { is64 = 0; break; }
        }
        g_is64 = is64;
    }
}
__device__ __forceinline__ int edge_src(const int* w, int E, int e) {
    return g_is64 ? w[2 * e] : w[e];
}
__device__ __forceinline__ int edge_dst(const int* w, int E, int e) {
    return g_is64 ? w[2 * (E + e)] : w[E + e];
}

// ---------------- CSR build ----------------
__global__ void k_count(const int* __restrict__ w, int E) {
    int e = blockIdx.x * blockDim.x + threadIdx.x;
    if (e < E) atomicAdd(&g_deg[edge_dst(w, E, e)], 1);
}
__global__ void k_part_sum() {
    __shared__ int sm[8];
    int i = blockIdx.x * 256 + threadIdx.x;
    int v = (i < NN) ? g_deg[i] : 0;
#pragma unroll
    for (int off = 16; off; off >>= 1) v += __shfl_xor_sync(0xffffffffu, v, off);
    if ((threadIdx.x & 31) == 0) sm[threadIdx.x >> 5] = v;
    __syncthreads();
    if (threadIdx.x == 0) {
        int s = 0;
#pragma unroll
        for (int k = 0; k < 8; k++) s += sm[k];
        g_part[blockIdx.x] = s;
    }
}
__global__ void k_part_scan() {
    __shared__ int buf[512];
    int t = threadIdx.x;
    buf[t] = (t < NB_SCAN) ? g_part[t] : 0;
    __syncthreads();
    for (int off = 1; off < 512; off <<= 1) {
        int v = (t >= off) ? buf[t - off] : 0;
        __syncthreads();
        buf[t] += v;
        __syncthreads();
    }
    if (t < NB_SCAN) g_partpre[t] = buf[t] - g_part[t];
}
__global__ void k_row_write(int E) {
    __shared__ int buf[256];
    int t = threadIdx.x;
    int i = blockIdx.x * 256 + t;
    int d = (i < NN) ? g_deg[i] : 0;
    buf[t] = d;
    __syncthreads();
    for (int off = 1; off < 256; off <<= 1) {
        int v = (t >= off) ? buf[t - off] : 0;
        __syncthreads();
        buf[t] += v;
        __syncthreads();
    }
    if (i < NN) {
        g_rowstart[i] = g_partpre[blockIdx.x] + buf[t] - d;
        if (i == NN - 1) g_rowstart[NN] = E;
    }
}
__global__ void k_fill(const int* __restrict__ w, int E) {
    int e = blockIdx.x * blockDim.x + threadIdx.x;
    if (e < E) {
        int src = edge_src(w, E, e);
        int dst = edge_dst(w, E, e);
        int pos = g_rowstart[dst] + atomicAdd(&g_cur[dst], 1);
        g_col[pos] = src;
    }
}

// ---------------- conversions ----------------
__global__ void k_cvt_x(const float* __restrict__ x) {
    size_t i = (size_t)blockIdx.x * blockDim.x + threadIdx.x;
    if (i < (size_t)NN * 128) g_xb[i] = __float2bfloat16(x[i]);
}
__global__ void k_cvtw(const float* __restrict__ Wl, const float* __restrict__ Wr,
                       int dst_id, int K2, int N, int stackK) {
    int idx = blockIdx.x * blockDim.x + threadIdx.x;
    if (idx >= N * K2) return;
    int n = idx / K2, k = idx % K2;
    float v;
    if (stackK) {
        int half = K2 / 2;
        v = (k < half) ? Wl[(size_t)k * N + n] : Wr[(size_t)(k - half) * N + n];
    } else {
        int half = N / 2;
        v = (n < half) ? Wl[(size_t)k * half + n] : Wr[(size_t)k * half + (n - half)];
    }
    bbuf(dst_id)[(size_t)n * K2 + k] = __float2bfloat16(v);
}

// ---------------- L1 pre-aggregation ----------------
__global__ void k_agg_pre() {
    int gw   = (blockIdx.x * blockDim.x + threadIdx.x) >> 5;
    int lane = threadIdx.x & 31;
    if (gw >= NN) return;
    int s = g_rowstart[gw], e = g_rowstart[gw + 1];
    float4 acc = make_float4(0.f, 0.f, 0.f, 0.f);
    for (int i = s; i < e; i++) {
        int nb = g_col[i];
        uint2 v = *(const uint2*)(g_xb + (size_t)nb * 128 + lane * 4);
        __nv_bfloat162 p0 = *reinterpret_cast<__nv_bfloat162*>(&v.x);
        __nv_bfloat162 p1 = *reinterpret_cast<__nv_bfloat162*>(&v.y);
        float2 f0 = __bfloat1622float2(p0);
        float2 f1 = __bfloat1622float2(p1);
        acc.x += f0.x; acc.y += f0.y; acc.z += f1.x; acc.w += f1.y;
    }
    float inv = 1.0f / (float)max(e - s, 1);
    __nv_bfloat162 o0, o1;
    o0.x = __float2bfloat16(acc.x * inv); o0.y = __float2bfloat16(acc.y * inv);
    o1.x = __float2bfloat16(acc.z * inv); o1.y = __float2bfloat16(acc.w * inv);
    uint2 ov;
    ov.x = *reinterpret_cast<unsigned*>(&o0);
    ov.y = *reinterpret_cast<unsigned*>(&o1);
    *(uint2*)(g_meanb + (size_t)gw * 128 + lane * 4) = ov;
}

// ---------------- bf16 GEMM v2: cp.async double-buffer + ldmatrix ----------------
// out[M,N] = [A0 | A1] @ Bt^T (+bias)(+relu). BM=128 BN=128 BK=32, 8 warps (4m x 2n).
#define SA 40   // smem row stride in halves (80B): conflict-free for ldmatrix

__device__ __forceinline__ void cpa16(__nv_bfloat16* s, const void* g, int valid) {
    unsigned sa = (unsigned)__cvta_generic_to_shared(s);
    asm volatile("cp.async.cg.shared.global [%0], [%1], 16, %2;\n"
                 :: "r"(sa), "l"(g), "r"(valid ? 16 : 0));
}
__device__ __forceinline__ void cpa_commit() {
    asm volatile("cp.async.commit_group;\n");
}

__global__ void __launch_bounds__(256, 2)
k_gemm_bf16(int a0_id, int a1_id, int Ka, int b_id,
            const float* __restrict__ bias,
            int outb_id,          // >=0: bf16 out buffer id; <0: fp32 out g_t
            int M, int N, int K2, int do_relu) {
    const __nv_bfloat16* A0 = bbuf(a0_id);
    const __nv_bfloat16* A1 = bbuf(a1_id);
    const __nv_bfloat16* Bt = bbuf(b_id);
    const int sA0 = Ka, sA1 = K2 - Ka;

    constexpr int BM = 128, BN = 128, BK = 32;
    __shared__ __nv_bfloat16 As[2][BM * SA];
    __shared__ __nv_bfloat16 Bs[2][BN * SA];

    const int tid  = threadIdx.x;
    const int lane = tid & 31;
    const int warp = tid >> 5;
    const int wm   = warp & 3;    // 0..3: 32-row slab
    const int wn   = warp >> 2;   // 0..1: 64-col slab
    const int gid  = lane >> 2;
    const int tig  = lane & 3;

    const int blockRow = blockIdx.x * BM;
    const int blockCol = blockIdx.y * BN;

    float c[2][8][4];
#pragma unroll
    for (int mt = 0; mt < 2; mt++)
#pragma unroll
        for (int nt = 0; nt < 8; nt++)
#pragma unroll
            for (int r = 0; r < 4; r++) c[mt][nt][r] = 0.f;

    const int T = K2 / BK;

    // cp.async chunk mapping: 512 16B-chunks per tile, 2 per thread (strided).
    // chunk f: row = f>>2, k-chunk = f&3 (8 halves each)
    auto load_tile = [&](int t, int stg) {
        const int kk = t * BK;
#pragma unroll
        for (int j = 0; j < 2; j++) {
            int f = tid + 256 * j;
            int r = f >> 2, c16 = f & 3;
            int gk = kk + c16 * 8;
            int grow = blockRow + r;
            int valid = grow < M;
            int rr = valid ? grow : 0;
            const __nv_bfloat16* p = (gk < Ka) ? (A0 + (size_t)rr * sA0 + gk)
                                               : (A1 + (size_t)rr * sA1 + (gk - Ka));
            cpa16(&As[stg][r * SA + c16 * 8], p, valid);
        }
#pragma unroll
        for (int j = 0; j < 2; j++) {
            int f = tid + 256 * j;
            int r = f >> 2, c16 = f & 3;
            int gk = kk + c16 * 8;
            cpa16(&Bs[stg][r * SA + c16 * 8],
                  Bt + (size_t)(blockCol + r) * K2 + gk, 1);
        }
        cpa_commit();
    };

    load_tile(0, 0);

    for (int t = 0; t < T; t++) {
        const int cur = t & 1;
        if (t + 1 < T) {
            load_tile(t + 1, cur ^ 1);
            asm volatile("cp.async.wait_group 1;\n");
        } else {
            asm volatile("cp.async.wait_group 0;\n");
        }
        __syncthreads();

        const __nv_bfloat16* as = As[cur];
        const __nv_bfloat16* bs = Bs[cur];

#pragma unroll
        for (int ks = 0; ks < BK; ks += 16) {
            unsigned af[2][4], bf[8][2];
#pragma unroll
            for (int mt = 0; mt < 2; mt++) {
                int row = wm * 32 + mt * 16 + (lane & 15);
                unsigned sa = (unsigned)__cvta_generic_to_shared(
                    as + row * SA + ks + (lane >> 4) * 8);
                asm volatile("ldmatrix.sync.aligned.m8n8.x4.shared.b16 {%0,%1,%2,%3}, [%4];"
                             : "=r"(af[mt][0]), "=r"(af[mt][1]),
                               "=r"(af[mt][2]), "=r"(af[mt][3])
                             : "r"(sa));
            }
#pragma unroll
            for (int np = 0; np < 4; np++) {
                int nrow = wn * 64 + np * 16 + (lane & 15);
                unsigned sb = (unsigned)__cvta_generic_to_shared(
                    bs + nrow * SA + ks + (lane >> 4) * 8);
                unsigned r0, r1, r2, r3;
                asm volatile("ldmatrix.sync.aligned.m8n8.x4.shared.b16 {%0,%1,%2,%3}, [%4];"
                             : "=r"(r0), "=r"(r1), "=r"(r2), "=r"(r3)
                             : "r"(sb));
                bf[2 * np + 0][0] = r0; bf[2 * np + 0][1] = r2;
                bf[2 * np + 1][0] = r1; bf[2 * np + 1][1] = r3;
            }
#pragma unroll
            for (int mt = 0; mt < 2; mt++)
#pragma unroll
                for (int nt = 0; nt < 8; nt++) {
                    asm volatile(
                        "mma.sync.aligned.m16n8k16.row.col.f32.bf16.bf16.f32 "
                        "{%0,%1,%2,%3}, {%4,%5,%6,%7}, {%8,%9}, {%0,%1,%2,%3};\n"
                        : "+f"(c[mt][nt][0]), "+f"(c[mt][nt][1]),
                          "+f"(c[mt][nt][2]), "+f"(c[mt][nt][3])
                        : "r"(af[mt][0]), "r"(af[mt][1]), "r"(af[mt][2]), "r"(af[mt][3]),
                          "r"(bf[nt][0]), "r"(bf[nt][1]));
                }
        }
        __syncthreads();
    }

    // epilogue
    __nv_bfloat16* outb = (outb_id >= 0) ? bbuf(outb_id) : nullptr;
#pragma unroll
    for (int nt = 0; nt < 8; nt++) {
        int col = blockCol + wn * 64 + nt * 8 + 2 * tig;
        float bv0 = bias ? bias[col] : 0.f;
        float bv1 = bias ? bias[col + 1] : 0.f;
#pragma unroll
        for (int mt = 0; mt < 2; mt++) {
#pragma unroll
            for (int h = 0; h < 2; h++) {
                int r = blockRow + wm * 32 + mt * 16 + gid + h * 8;
                if (r < M) {
                    float v0 = c[mt][nt][2 * h + 0] + bv0;
                    float v1 = c[mt][nt][2 * h + 1] + bv1;
                    if (do_relu) { v0 = fmaxf(v0, 0.f); v1 = fmaxf(v1, 0.f); }
                    if (outb) {
                        __nv_bfloat162 o;
                        o.x = __float2bfloat16(v0);
                        o.y = __float2bfloat16(v1);
                        *(unsigned*)(outb + (size_t)r * N + col) =
                            *reinterpret_cast<unsigned*>(&o);
                    } else {
                        float2 o = make_float2(v0, v1);
                        *(float2*)(g_t + (size_t)r * N + col) = o;
                    }
                }
            }
        }
    }
}

// ---------------- agg-combine ----------------
template <int C, int MODE>
__global__ void k_agg_combine(const float* __restrict__ bias, float* __restrict__ out) {
    int gw   = (blockIdx.x * blockDim.x + threadIdx.x) >> 5;
    int lane = threadIdx.x & 31;
    if (gw >= NN) return;
    int s = g_rowstart[gw], e = g_rowstart[gw + 1];
    constexpr int TC = 2 * C;

    if (MODE == 0) {
        float4 acc = make_float4(0.f, 0.f, 0.f, 0.f);
        for (int i = s; i < e; i++) {
            int nb = g_col[i];
            float4 v = *(const float4*)(g_t + (size_t)nb * TC + lane * 4);
            acc.x += v.x; acc.y += v.y; acc.z += v.z; acc.w += v.w;
        }
        float inv = 1.0f / (float)max(e - s, 1);
        float4 sv = *(const float4*)(g_t + (size_t)gw * TC + C + lane * 4);
        float4 bv = *(const float4*)(bias + lane * 4);
        float v0 = fmaxf(acc.x * inv + sv.x + bv.x, 0.f);
        float v1 = fmaxf(acc.y * inv + sv.y + bv.y, 0.f);
        float v2 = fmaxf(acc.z * inv + sv.z + bv.z, 0.f);
        float v3 = fmaxf(acc.w * inv + sv.w + bv.w, 0.f);
        __nv_bfloat162 o0, o1;
        o0.x = __float2bfloat16(v0); o0.y = __float2bfloat16(v1);
        o1.x = __float2bfloat16(v2); o1.y = __float2bfloat16(v3);
        uint2 ov;
        ov.x = *reinterpret_cast<unsigned*>(&o0);
        ov.y = *reinterpret_cast<unsigned*>(&o1);
        *(uint2*)(g_h2b + (size_t)gw * C + lane * 4) = ov;
    } else {
        float2 acc = make_float2(0.f, 0.f);
        for (int i = s; i < e; i++) {
            int nb = g_col[i];
            float2 v = *(const float2*)(g_t + (size_t)nb * TC + lane * 2);
            acc.x += v.x; acc.y += v.y;
        }
        float inv = 1.0f / (float)max(e - s, 1);
        float2 sv = *(const float2*)(g_t + (size_t)gw * TC + C + lane * 2);
        float2 bv = *(const float2*)(bias + lane * 2);
        float v0 = acc.x * inv + sv.x + bv.x;
        float v1 = acc.y * inv + sv.y + bv.y;
        float m = fmaxf(v0, v1);
#pragma unroll
        for (int off = 16; off; off >>= 1) m = fmaxf(m, __shfl_xor_sync(0xffffffffu, m, off));
        float sum = __expf(v0 - m) + __expf(v1 - m);
#pragma unroll
        for (int off = 16; off; off >>= 1) sum += __shfl_xor_sync(0xffffffffu, sum, off);
        float lse = m + __logf(sum);
        float2 o = make_float2(v0 - lse, v1 - lse);
        *(float2*)(out + (size_t)gw * C + lane * 2) = o;
    }
}

// ---------------- launch ----------------
extern "C" void kernel_launch(void* const* d_in, const int* in_sizes, int n_in,
                              void* d_out, int out_size) {
    const float* x   = (const float*)d_in[0];
    const int*   ei  = (const int*)d_in[1];
    const float* W1l = (const float*)d_in[2];
    const float* W1r = (const float*)d_in[3];
    const float* b1  = (const float*)d_in[4];
    const float* W2l = (const float*)d_in[5];
    const float* W2r = (const float*)d_in[6];
    const float* b2  = (const float*)d_in[7];
    const float* W3l = (const float*)d_in[8];
    const float* W3r = (const float*)d_in[9];
    const float* b3  = (const float*)d_in[10];
    float* out = (float*)d_out;

    int E = in_sizes[1] / 2;

    // CSR build
    k_init<<<(NN + 255) / 256, 256>>>(ei);
    k_count<<<(E + 255) / 256, 256>>>(ei, E);
    k_part_sum<<<NB_SCAN, 256>>>();
    k_part_scan<<<1, 512>>>();
    k_row_write<<<NB_SCAN, 256>>>(E);
    k_fill<<<(E + 255) / 256, 256>>>(ei, E);

    // conversions
    k_cvt_x<<<(NN * 128 + 255) / 256, 256>>>(x);
    k_cvtw<<<(256 * 256 + 255) / 256, 256>>>(W1l, W1r, 4, 256, 256, 1);
    k_cvtw<<<(256 * 256 + 255) / 256, 256>>>(W2l, W2r, 5, 256, 256, 0);
    k_cvtw<<<(128 * 128 + 255) / 256, 256>>>(W3l, W3r, 6, 128, 128, 0);

    int aggBlocks = (NN * 32 + 255) / 256;

    // Layer 1: pre-agg + dual-A GEMM -> h1b (relu)
    k_agg_pre<<<aggBlocks, 256>>>();
    {
        dim3 grid((NN + 127) / 128, 256 / 128);
        k_gemm_bf16<<<grid, 256>>>(1, 0, 128, 4, b1, /*outb=*/2, NN, 256, 256, 1);
    }
    // Layer 2: GEMM -> t (fp32), agg-combine(relu) -> h2b
    {
        dim3 grid((NN + 127) / 128, 256 / 128);
        k_gemm_bf16<<<grid, 256>>>(2, 2, 256, 5, nullptr, /*outb=*/-1, NN, 256, 256, 0);
    }
    k_agg_combine<128, 0><<<aggBlocks, 256>>>(b2, nullptr);
    // Layer 3: GEMM -> t (fp32), agg-combine + log_softmax -> out
    {
        dim3 grid((NN + 127) / 128, 128 / 128);
        k_gemm_bf16<<<grid, 256>>>(3, 3, 128, 6, nullptr, /*outb=*/-1, NN, 128, 128, 0);
    }
    k_agg_combine<64, 1><<<aggBlocks, 256>>>(b3, out);
}

// round 9
// speedup vs baseline: 3.8652x; 1.1005x over previous
#include <cuda_runtime.h>
#include <cuda_bf16.h>
#include <math.h>

#define NN 100000
#define EE 600000
#define NB_SCAN ((NN + 255) / 256)   // 391

// ---------------- static scratch (no allocations allowed) ----------------
__device__ int   g_is64;
__device__ int   g_deg[NN];
__device__ int   g_cur[NN];
__device__ int   g_rowstart[NN + 1];
__device__ int   g_col[EE];
__device__ int   g_part[512];

__device__ __nv_bfloat16 g_xb[(size_t)NN * 128];
__device__ __nv_bfloat16 g_meanb[(size_t)NN * 128];
__device__ __nv_bfloat16 g_h1b[(size_t)NN * 256];
__device__ __nv_bfloat16 g_h2b[(size_t)NN * 128];
__device__ float         g_t[(size_t)NN * 256];
__device__ __nv_bfloat16 g_wt1[256 * 256];
__device__ __nv_bfloat16 g_wt2[256 * 256];
__device__ __nv_bfloat16 g_wt3[128 * 128];

__device__ __forceinline__ __nv_bfloat16* bbuf(int id) {
    switch (id) {
        case 0: return g_xb;
        case 1: return g_meanb;
        case 2: return g_h1b;
        case 3: return g_h2b;
        case 4: return g_wt1;
        case 5: return g_wt2;
        default: return g_wt3;
    }
}

// ---------------- init: zero counts + dtype probe (fused) ----------------
__global__ void k_init(const int* __restrict__ w) {
    int i = blockIdx.x * blockDim.x + threadIdx.x;
    if (i < NN) { g_deg[i] = 0; g_cur[i] = 0; }
    if (i == 0) {
        int is64 = 1;
        for (int j = 0; j < 64; j++) {
            if (w[2 * j + 1] != 0) { is64 = 0; break; }
        }
        g_is64 = is64;
    }
}
__device__ __forceinline__ int edge_src(const int* w, int E, int e) {
    return g_is64 ? w[2 * e] : w[e];
}
__device__ __forceinline__ int edge_dst(const int* w, int E, int e) {
    return g_is64 ? w[2 * (E + e)] : w[E + e];
}

// ---------------- CSR build ----------------
__global__ void k_count(const int* __restrict__ w, int E) {
    int e = blockIdx.x * blockDim.x + threadIdx.x;
    if (e < E) atomicAdd(&g_deg[edge_dst(w, E, e)], 1);
}
__global__ void k_part_sum() {
    __shared__ int sm[8];
    int i = blockIdx.x * 256 + threadIdx.x;
    int v = (i < NN) ? g_deg[i] : 0;
#pragma unroll
    for (int off = 16; off; off >>= 1) v += __shfl_xor_sync(0xffffffffu, v, off);
    if ((threadIdx.x & 31) == 0) sm[threadIdx.x >> 5] = v;
    __syncthreads();
    if (threadIdx.x == 0) {
        int s = 0;
#pragma unroll
        for (int k = 0; k < 8; k++) s += sm[k];
        g_part[blockIdx.x] = s;
    }
}
// fused: per-block prefix-of-partials reduction + local scan + rowstart write
__global__ void k_row_write(int E) {
    __shared__ int red[8];
    __shared__ int buf[256];
    __shared__ int base_sh;
    int t = threadIdx.x;
    int b = blockIdx.x;

    // sum of g_part[0..b)
    int acc = 0;
    for (int j = t; j < b; j += 256) acc += g_part[j];
#pragma unroll
    for (int off = 16; off; off >>= 1) acc += __shfl_xor_sync(0xffffffffu, acc, off);
    if ((t & 31) == 0) red[t >> 5] = acc;
    __syncthreads();
    if (t == 0) {
        int s = 0;
#pragma unroll
        for (int k = 0; k < 8; k++) s += red[k];
        base_sh = s;
    }

    int i = b * 256 + t;
    int d = (i < NN) ? g_deg[i] : 0;
    buf[t] = d;
    __syncthreads();
    for (int off = 1; off < 256; off <<= 1) {
        int v = (t >= off) ? buf[t - off] : 0;
        __syncthreads();
        buf[t] += v;
        __syncthreads();
    }
    if (i < NN) {
        g_rowstart[i] = base_sh + buf[t] - d;
        if (i == NN - 1) g_rowstart[NN] = E;
    }
}
__global__ void k_fill(const int* __restrict__ w, int E) {
    int e = blockIdx.x * blockDim.x + threadIdx.x;
    if (e < E) {
        int src = edge_src(w, E, e);
        int dst = edge_dst(w, E, e);
        int pos = g_rowstart[dst] + atomicAdd(&g_cur[dst], 1);
        g_col[pos] = src;
    }
}

// ---------------- conversions ----------------
__global__ void k_cvt_x(const float* __restrict__ x) {
    size_t i = (size_t)blockIdx.x * blockDim.x + threadIdx.x;
    if (i < (size_t)NN * 32) {
        float4 v = *(const float4*)(x + i * 4);
        __nv_bfloat162 o0, o1;
        o0.x = __float2bfloat16(v.x); o0.y = __float2bfloat16(v.y);
        o1.x = __float2bfloat16(v.z); o1.y = __float2bfloat16(v.w);
        uint2 ov;
        ov.x = *reinterpret_cast<unsigned*>(&o0);
        ov.y = *reinterpret_cast<unsigned*>(&o1);
        *(uint2*)(g_xb + i * 4) = ov;
    }
}
__global__ void k_cvtw(const float* __restrict__ Wl, const float* __restrict__ Wr,
                       int dst_id, int K2, int N, int stackK) {
    int idx = blockIdx.x * blockDim.x + threadIdx.x;
    if (idx >= N * K2) return;
    int n = idx / K2, k = idx % K2;
    float v;
    if (stackK) {
        int half = K2 / 2;
        v = (k < half) ? Wl[(size_t)k * N + n] : Wr[(size_t)(k - half) * N + n];
    } else {
        int half = N / 2;
        v = (n < half) ? Wl[(size_t)k * half + n] : Wr[(size_t)k * half + (n - half)];
    }
    bbuf(dst_id)[(size_t)n * K2 + k] = __float2bfloat16(v);
}

// ---------------- L1 pre-aggregation ----------------
__global__ void k_agg_pre() {
    int gw   = (blockIdx.x * blockDim.x + threadIdx.x) >> 5;
    int lane = threadIdx.x & 31;
    if (gw >= NN) return;
    int s = g_rowstart[gw], e = g_rowstart[gw + 1];
    float4 acc = make_float4(0.f, 0.f, 0.f, 0.f);
    for (int i = s; i < e; i++) {
        int nb = g_col[i];
        uint2 v = *(const uint2*)(g_xb + (size_t)nb * 128 + lane * 4);
        __nv_bfloat162 p0 = *reinterpret_cast<__nv_bfloat162*>(&v.x);
        __nv_bfloat162 p1 = *reinterpret_cast<__nv_bfloat162*>(&v.y);
        float2 f0 = __bfloat1622float2(p0);
        float2 f1 = __bfloat1622float2(p1);
        acc.x += f0.x; acc.y += f0.y; acc.z += f1.x; acc.w += f1.y;
    }
    float inv = 1.0f / (float)max(e - s, 1);
    __nv_bfloat162 o0, o1;
    o0.x = __float2bfloat16(acc.x * inv); o0.y = __float2bfloat16(acc.y * inv);
    o1.x = __float2bfloat16(acc.z * inv); o1.y = __float2bfloat16(acc.w * inv);
    uint2 ov;
    ov.x = *reinterpret_cast<unsigned*>(&o0);
    ov.y = *reinterpret_cast<unsigned*>(&o1);
    *(uint2*)(g_meanb + (size_t)gw * 128 + lane * 4) = ov;
}

// ---------------- bf16 GEMM: cp.async double-buffer + ldmatrix ----------------
#define SA 40   // smem row stride in halves (80B): conflict-free for ldmatrix

__device__ __forceinline__ void cpa16(__nv_bfloat16* s, const void* g, int valid) {
    unsigned sa = (unsigned)__cvta_generic_to_shared(s);
    asm volatile("cp.async.cg.shared.global [%0], [%1], 16, %2;\n"
                 :: "r"(sa), "l"(g), "r"(valid ? 16 : 0));
}
__device__ __forceinline__ void cpa_commit() {
    asm volatile("cp.async.commit_group;\n");
}

__global__ void __launch_bounds__(256, 2)
k_gemm_bf16(int a0_id, int a1_id, int Ka, int b_id,
            const float* __restrict__ bias,
            int outb_id,          // >=0: bf16 out buffer id; <0: fp32 out g_t
            int M, int N, int K2, int do_relu) {
    const __nv_bfloat16* A0 = bbuf(a0_id);
    const __nv_bfloat16* A1 = bbuf(a1_id);
    const __nv_bfloat16* Bt = bbuf(b_id);
    const int sA0 = Ka, sA1 = K2 - Ka;

    constexpr int BM = 128, BN = 128, BK = 32;
    __shared__ __nv_bfloat16 As[2][BM * SA];
    __shared__ __nv_bfloat16 Bs[2][BN * SA];

    const int tid  = threadIdx.x;
    const int lane = tid & 31;
    const int warp = tid >> 5;
    const int wm   = warp & 3;
    const int wn   = warp >> 2;
    const int gid  = lane >> 2;
    const int tig  = lane & 3;

    const int blockRow = blockIdx.x * BM;
    const int blockCol = blockIdx.y * BN;

    float c[2][8][4];
#pragma unroll
    for (int mt = 0; mt < 2; mt++)
#pragma unroll
        for (int nt = 0; nt < 8; nt++)
#pragma unroll
            for (int r = 0; r < 4; r++) c[mt][nt][r] = 0.f;

    const int T = K2 / BK;

    auto load_tile = [&](int t, int stg) {
        const int kk = t * BK;
#pragma unroll
        for (int j = 0; j < 2; j++) {
            int f = tid + 256 * j;
            int r = f >> 2, c16 = f & 3;
            int gk = kk + c16 * 8;
            int grow = blockRow + r;
            int valid = grow < M;
            int rr = valid ? grow : 0;
            const __nv_bfloat16* p = (gk < Ka) ? (A0 + (size_t)rr * sA0 + gk)
                                               : (A1 + (size_t)rr * sA1 + (gk - Ka));
            cpa16(&As[stg][r * SA + c16 * 8], p, valid);
        }
#pragma unroll
        for (int j = 0; j < 2; j++) {
            int f = tid + 256 * j;
            int r = f >> 2, c16 = f & 3;
            int gk = kk + c16 * 8;
            cpa16(&Bs[stg][r * SA + c16 * 8],
                  Bt + (size_t)(blockCol + r) * K2 + gk, 1);
        }
        cpa_commit();
    };

    load_tile(0, 0);

    for (int t = 0; t < T; t++) {
        const int cur = t & 1;
        if (t + 1 < T) {
            load_tile(t + 1, cur ^ 1);
            asm volatile("cp.async.wait_group 1;\n");
        } else {
            asm volatile("cp.async.wait_group 0;\n");
        }
        __syncthreads();

        const __nv_bfloat16* as = As[cur];
        const __nv_bfloat16* bs = Bs[cur];

#pragma unroll
        for (int ks = 0; ks < BK; ks += 16) {
            unsigned af[2][4], bf[8][2];
#pragma unroll
            for (int mt = 0; mt < 2; mt++) {
                int row = wm * 32 + mt * 16 + (lane & 15);
                unsigned sa = (unsigned)__cvta_generic_to_shared(
                    as + row * SA + ks + (lane >> 4) * 8);
                asm volatile("ldmatrix.sync.aligned.m8n8.x4.shared.b16 {%0,%1,%2,%3}, [%4];"
                             : "=r"(af[mt][0]), "=r"(af[mt][1]),
                               "=r"(af[mt][2]), "=r"(af[mt][3])
                             : "r"(sa));
            }
#pragma unroll
            for (int np = 0; np < 4; np++) {
                int nrow = wn * 64 + np * 16 + (lane & 15);
                unsigned sb = (unsigned)__cvta_generic_to_shared(
                    bs + nrow * SA + ks + (lane >> 4) * 8);
                unsigned r0, r1, r2, r3;
                asm volatile("ldmatrix.sync.aligned.m8n8.x4.shared.b16 {%0,%1,%2,%3}, [%4];"
                             : "=r"(r0), "=r"(r1), "=r"(r2), "=r"(r3)
                             : "r"(sb));
                bf[2 * np + 0][0] = r0; bf[2 * np + 0][1] = r2;
                bf[2 * np + 1][0] = r1; bf[2 * np + 1][1] = r3;
            }
#pragma unroll
            for (int mt = 0; mt < 2; mt++)
#pragma unroll
                for (int nt = 0; nt < 8; nt++) {
                    asm volatile(
                        "mma.sync.aligned.m16n8k16.row.col.f32.bf16.bf16.f32 "
                        "{%0,%1,%2,%3}, {%4,%5,%6,%7}, {%8,%9}, {%0,%1,%2,%3};\n"
                        : "+f"(c[mt][nt][0]), "+f"(c[mt][nt][1]),
                          "+f"(c[mt][nt][2]), "+f"(c[mt][nt][3])
                        : "r"(af[mt][0]), "r"(af[mt][1]), "r"(af[mt][2]), "r"(af[mt][3]),
                          "r"(bf[nt][0]), "r"(bf[nt][1]));
                }
        }
        __syncthreads();
    }

    // epilogue
    __nv_bfloat16* outb = (outb_id >= 0) ? bbuf(outb_id) : nullptr;
#pragma unroll
    for (int nt = 0; nt < 8; nt++) {
        int col = blockCol + wn * 64 + nt * 8 + 2 * tig;
        float bv0 = bias ? bias[col] : 0.f;
        float bv1 = bias ? bias[col + 1] : 0.f;
#pragma unroll
        for (int mt = 0; mt < 2; mt++) {
#pragma unroll
            for (int h = 0; h < 2; h++) {
                int r = blockRow + wm * 32 + mt * 16 + gid + h * 8;
                if (r < M) {
                    float v0 = c[mt][nt][2 * h + 0] + bv0;
                    float v1 = c[mt][nt][2 * h + 1] + bv1;
                    if (do_relu) { v0 = fmaxf(v0, 0.f); v1 = fmaxf(v1, 0.f); }
                    if (outb) {
                        __nv_bfloat162 o;
                        o.x = __float2bfloat16(v0);
                        o.y = __float2bfloat16(v1);
                        *(unsigned*)(outb + (size_t)r * N + col) =
                            *reinterpret_cast<unsigned*>(&o);
                    } else {
                        float2 o = make_float2(v0, v1);
                        *(float2*)(g_t + (size_t)r * N + col) = o;
                    }
                }
            }
        }
    }
}

// ---------------- agg-combine ----------------
template <int C, int MODE>
__global__ void k_agg_combine(const float* __restrict__ bias, float* __restrict__ out) {
    int gw   = (blockIdx.x * blockDim.x + threadIdx.x) >> 5;
    int lane = threadIdx.x & 31;
    if (gw >= NN) return;
    int s = g_rowstart[gw], e = g_rowstart[gw + 1];
    constexpr int TC = 2 * C;

    if (MODE == 0) {
        float4 acc = make_float4(0.f, 0.f, 0.f, 0.f);
        for (int i = s; i < e; i++) {
            int nb = g_col[i];
            float4 v = *(const float4*)(g_t + (size_t)nb * TC + lane * 4);
            acc.x += v.x; acc.y += v.y; acc.z += v.z; acc.w += v.w;
        }
        float inv = 1.0f / (float)max(e - s, 1);
        float4 sv = *(const float4*)(g_t + (size_t)gw * TC + C + lane * 4);
        float4 bv = *(const float4*)(bias + lane * 4);
        float v0 = fmaxf(acc.x * inv + sv.x + bv.x, 0.f);
        float v1 = fmaxf(acc.y * inv + sv.y + bv.y, 0.f);
        float v2 = fmaxf(acc.z * inv + sv.z + bv.z, 0.f);
        float v3 = fmaxf(acc.w * inv + sv.w + bv.w, 0.f);
        __nv_bfloat162 o0, o1;
        o0.x = __float2bfloat16(v0); o0.y = __float2bfloat16(v1);
        o1.x = __float2bfloat16(v2); o1.y = __float2bfloat16(v3);
        uint2 ov;
        ov.x = *reinterpret_cast<unsigned*>(&o0);
        ov.y = *reinterpret_cast<unsigned*>(&o1);
        *(uint2*)(g_h2b + (size_t)gw * C + lane * 4) = ov;
    } else {
        float2 acc = make_float2(0.f, 0.f);
        for (int i = s; i < e; i++) {
            int nb = g_col[i];
            float2 v = *(const float2*)(g_t + (size_t)nb * TC + lane * 2);
            acc.x += v.x; acc.y += v.y;
        }
        float inv = 1.0f / (float)max(e - s, 1);
        float2 sv = *(const float2*)(g_t + (size_t)gw * TC + C + lane * 2);
        float2 bv = *(const float2*)(bias + lane * 2);
        float v0 = acc.x * inv + sv.x + bv.x;
        float v1 = acc.y * inv + sv.y + bv.y;
        float m = fmaxf(v0, v1);
#pragma unroll
        for (int off = 16; off; off >>= 1) m = fmaxf(m, __shfl_xor_sync(0xffffffffu, m, off));
        float sum = __expf(v0 - m) + __expf(v1 - m);
#pragma unroll
        for (int off = 16; off; off >>= 1) sum += __shfl_xor_sync(0xffffffffu, sum, off);
        float lse = m + __logf(sum);
        float2 o = make_float2(v0 - lse, v1 - lse);
        *(float2*)(out + (size_t)gw * C + lane * 2) = o;
    }
}

// ---------------- launch ----------------
extern "C" void kernel_launch(void* const* d_in, const int* in_sizes, int n_in,
                              void* d_out, int out_size) {
    const float* x   = (const float*)d_in[0];
    const int*   ei  = (const int*)d_in[1];
    const float* W1l = (const float*)d_in[2];
    const float* W1r = (const float*)d_in[3];
    const float* b1  = (const float*)d_in[4];
    const float* W2l = (const float*)d_in[5];
    const float* W2r = (const float*)d_in[6];
    const float* b2  = (const float*)d_in[7];
    const float* W3l = (const float*)d_in[8];
    const float* W3r = (const float*)d_in[9];
    const float* b3  = (const float*)d_in[10];
    float* out = (float*)d_out;

    int E = in_sizes[1] / 2;

    // side streams + events for fork-join under graph capture (host objects;
    // created once, outside any capture since the first call is the correctness run)
    static cudaStream_t s1 = nullptr, s2 = nullptr;
    static cudaEvent_t eFork = nullptr, eCvtX = nullptr, eCvtW = nullptr;
    if (!s1) {
        cudaStreamCreateWithFlags(&s1, cudaStreamNonBlocking);
        cudaStreamCreateWithFlags(&s2, cudaStreamNonBlocking);
        cudaEventCreateWithFlags(&eFork, cudaEventDisableTiming);
        cudaEventCreateWithFlags(&eCvtX, cudaEventDisableTiming);
        cudaEventCreateWithFlags(&eCvtW, cudaEventDisableTiming);
    }

    // fork
    cudaEventRecord(eFork, 0);
    cudaStreamWaitEvent(s1, eFork, 0);
    cudaStreamWaitEvent(s2, eFork, 0);

    // s1: x -> bf16
    k_cvt_x<<<(NN * 32 + 255) / 256, 256, 0, s1>>>(x);
    cudaEventRecord(eCvtX, s1);

    // s2: weight transposes -> bf16
    k_cvtw<<<(256 * 256 + 255) / 256, 256, 0, s2>>>(W1l, W1r, 4, 256, 256, 1);
    k_cvtw<<<(256 * 256 + 255) / 256, 256, 0, s2>>>(W2l, W2r, 5, 256, 256, 0);
    k_cvtw<<<(128 * 128 + 255) / 256, 256, 0, s2>>>(W3l, W3r, 6, 128, 128, 0);
    cudaEventRecord(eCvtW, s2);

    // main stream: CSR build
    k_init<<<(NN + 255) / 256, 256>>>(ei);
    k_count<<<(E + 255) / 256, 256>>>(ei, E);
    k_part_sum<<<NB_SCAN, 256>>>();
    k_row_write<<<NB_SCAN, 256>>>(E);
    k_fill<<<(E + 255) / 256, 256>>>(ei, E);

    // join: agg_pre needs g_xb + CSR; gemm1 additionally needs weights
    cudaStreamWaitEvent(0, eCvtX, 0);

    int aggBlocks = (NN * 32 + 255) / 256;

    // Layer 1: pre-agg + dual-A GEMM -> h1b (relu)
    k_agg_pre<<<aggBlocks, 256>>>();
    cudaStreamWaitEvent(0, eCvtW, 0);
    {
        dim3 grid((NN + 127) / 128, 256 / 128);
        k_gemm_bf16<<<grid, 256>>>(1, 0, 128, 4, b1, /*outb=*/2, NN, 256, 256, 1);
    }
    // Layer 2: GEMM -> t (fp32), agg-combine(relu) -> h2b
    {
        dim3 grid((NN + 127) / 128, 256 / 128);
        k_gemm_bf16<<<grid, 256>>>(2, 2, 256, 5, nullptr, /*outb=*/-1, NN, 256, 256, 0);
    }
    k_agg_combine<128, 0><<<aggBlocks, 256>>>(b2, nullptr);
    // Layer 3: GEMM -> t (fp32), agg-combine + log_softmax -> out
    {
        dim3 grid((NN + 127) / 128, 128 / 128);
        k_gemm_bf16<<<grid, 256>>>(3, 3, 128, 6, nullptr, /*outb=*/-1, NN, 128, 128, 0);
    }
    k_agg_combine<64, 1><<<aggBlocks, 256>>>(b3, out);
}

// round 10
// speedup vs baseline: 4.0390x; 1.0450x over previous
#include <cuda_runtime.h>
#include <cuda_bf16.h>
#include <math.h>

#define NN 100000
#define EE 600000
#define NB_SCAN ((NN + 255) / 256)   // 391

// ---------------- static scratch (no allocations allowed) ----------------
__device__ int   g_is64;
__device__ int   g_deg[NN];
__device__ int   g_cur[NN];
__device__ int   g_rowstart[NN + 1];
__device__ int   g_col[EE];
__device__ int   g_part[512];

__device__ __nv_bfloat16 g_xb[(size_t)NN * 128];
__device__ __nv_bfloat16 g_meanb[(size_t)NN * 128];
__device__ __nv_bfloat16 g_h1b[(size_t)NN * 256];
__device__ __nv_bfloat16 g_h2b[(size_t)NN * 128];
__device__ __nv_bfloat16 g_tb[(size_t)NN * 128];   // bf16 mean-term (Wl half)
__device__ float         g_t[(size_t)NN * 128];    // fp32 self-term (Wr half)
__device__ __nv_bfloat16 g_wt1[256 * 256];
__device__ __nv_bfloat16 g_wt2[256 * 256];
__device__ __nv_bfloat16 g_wt3[128 * 128];

__device__ __forceinline__ __nv_bfloat16* bbuf(int id) {
    switch (id) {
        case 0: return g_xb;
        case 1: return g_meanb;
        case 2: return g_h1b;
        case 3: return g_h2b;
        case 4: return g_wt1;
        case 5: return g_wt2;
        default: return g_wt3;
    }
}

// ---------------- init: zero counts + dtype probe (fused) ----------------
__global__ void k_init(const int* __restrict__ w) {
    int i = blockIdx.x * blockDim.x + threadIdx.x;
    if (i < NN) { g_deg[i] = 0; g_cur[i] = 0; }
    if (i == 0) {
        int is64 = 1;
        for (int j = 0; j < 64; j++) {
            if (w[2 * j + 1] != 0) { is64 = 0; break; }
        }
        g_is64 = is64;
    }
}
__device__ __forceinline__ int edge_src(const int* w, int E, int e) {
    return g_is64 ? w[2 * e] : w[e];
}
__device__ __forceinline__ int edge_dst(const int* w, int E, int e) {
    return g_is64 ? w[2 * (E + e)] : w[E + e];
}

// ---------------- CSR build ----------------
__global__ void k_count(const int* __restrict__ w, int E) {
    int e = blockIdx.x * blockDim.x + threadIdx.x;
    if (e < E) atomicAdd(&g_deg[edge_dst(w, E, e)], 1);
}
__global__ void k_part_sum() {
    __shared__ int sm[8];
    int i = blockIdx.x * 256 + threadIdx.x;
    int v = (i < NN) ? g_deg[i] : 0;
#pragma unroll
    for (int off = 16; off; off >>= 1) v += __shfl_xor_sync(0xffffffffu, v, off);
    if ((threadIdx.x & 31) == 0) sm[threadIdx.x >> 5] = v;
    __syncthreads();
    if (threadIdx.x == 0) {
        int s = 0;
#pragma unroll
        for (int k = 0; k < 8; k++) s += sm[k];
        g_part[blockIdx.x] = s;
    }
}
__global__ void k_row_write(int E) {
    __shared__ int red[8];
    __shared__ int buf[256];
    __shared__ int base_sh;
    int t = threadIdx.x;
    int b = blockIdx.x;

    int acc = 0;
    for (int j = t; j < b; j += 256) acc += g_part[j];
#pragma unroll
    for (int off = 16; off; off >>= 1) acc += __shfl_xor_sync(0xffffffffu, acc, off);
    if ((t & 31) == 0) red[t >> 5] = acc;
    __syncthreads();
    if (t == 0) {
        int s = 0;
#pragma unroll
        for (int k = 0; k < 8; k++) s += red[k];
        base_sh = s;
    }

    int i = b * 256 + t;
    int d = (i < NN) ? g_deg[i] : 0;
    buf[t] = d;
    __syncthreads();
    for (int off = 1; off < 256; off <<= 1) {
        int v = (t >= off) ? buf[t - off] : 0;
        __syncthreads();
        buf[t] += v;
        __syncthreads();
    }
    if (i < NN) {
        g_rowstart[i] = base_sh + buf[t] - d;
        if (i == NN - 1) g_rowstart[NN] = E;
    }
}
__global__ void k_fill(const int* __restrict__ w, int E) {
    int e = blockIdx.x * blockDim.x + threadIdx.x;
    if (e < E) {
        int src = edge_src(w, E, e);
        int dst = edge_dst(w, E, e);
        int pos = g_rowstart[dst] + atomicAdd(&g_cur[dst], 1);
        g_col[pos] = src;
    }
}

// ---------------- conversions ----------------
__global__ void k_cvt_x(const float* __restrict__ x) {
    size_t i = (size_t)blockIdx.x * blockDim.x + threadIdx.x;
    if (i < (size_t)NN * 32) {
        float4 v = *(const float4*)(x + i * 4);
        __nv_bfloat162 o0, o1;
        o0.x = __float2bfloat16(v.x); o0.y = __float2bfloat16(v.y);
        o1.x = __float2bfloat16(v.z); o1.y = __float2bfloat16(v.w);
        uint2 ov;
        ov.x = *reinterpret_cast<unsigned*>(&o0);
        ov.y = *reinterpret_cast<unsigned*>(&o1);
        *(uint2*)(g_xb + i * 4) = ov;
    }
}
__global__ void k_cvtw(const float* __restrict__ Wl, const float* __restrict__ Wr,
                       int dst_id, int K2, int N, int stackK) {
    int idx = blockIdx.x * blockDim.x + threadIdx.x;
    if (idx >= N * K2) return;
    int n = idx / K2, k = idx % K2;
    float v;
    if (stackK) {
        int half = K2 / 2;
        v = (k < half) ? Wl[(size_t)k * N + n] : Wr[(size_t)(k - half) * N + n];
    } else {
        int half = N / 2;
        v = (n < half) ? Wl[(size_t)k * half + n] : Wr[(size_t)k * half + (n - half)];
    }
    bbuf(dst_id)[(size_t)n * K2 + k] = __float2bfloat16(v);
}

// ---------------- L1 pre-aggregation ----------------
__global__ void k_agg_pre() {
    int gw   = (blockIdx.x * blockDim.x + threadIdx.x) >> 5;
    int lane = threadIdx.x & 31;
    if (gw >= NN) return;
    int s = g_rowstart[gw], e = g_rowstart[gw + 1];
    float4 acc = make_float4(0.f, 0.f, 0.f, 0.f);
    for (int i = s; i < e; i++) {
        int nb = g_col[i];
        uint2 v = *(const uint2*)(g_xb + (size_t)nb * 128 + lane * 4);
        __nv_bfloat162 p0 = *reinterpret_cast<__nv_bfloat162*>(&v.x);
        __nv_bfloat162 p1 = *reinterpret_cast<__nv_bfloat162*>(&v.y);
        float2 f0 = __bfloat1622float2(p0);
        float2 f1 = __bfloat1622float2(p1);
        acc.x += f0.x; acc.y += f0.y; acc.z += f1.x; acc.w += f1.y;
    }
    float inv = 1.0f / (float)max(e - s, 1);
    __nv_bfloat162 o0, o1;
    o0.x = __float2bfloat16(acc.x * inv); o0.y = __float2bfloat16(acc.y * inv);
    o1.x = __float2bfloat16(acc.z * inv); o1.y = __float2bfloat16(acc.w * inv);
    uint2 ov;
    ov.x = *reinterpret_cast<unsigned*>(&o0);
    ov.y = *reinterpret_cast<unsigned*>(&o1);
    *(uint2*)(g_meanb + (size_t)gw * 128 + lane * 4) = ov;
}

// ---------------- bf16 GEMM: 3-stage cp.async + ldmatrix ----------------
#define SA 40   // smem row stride in halves (80B): 16B-aligned, conflict-free
#define GEMM_SMEM (3 * 256 * SA * 2)   // 61440 bytes

__device__ __forceinline__ void cpa16(__nv_bfloat16* s, const void* g, int valid) {
    unsigned sa = (unsigned)__cvta_generic_to_shared(s);
    asm volatile("cp.async.cg.shared.global [%0], [%1], 16, %2;\n"
                 :: "r"(sa), "l"(g), "r"(valid ? 16 : 0));
}

__global__ void __launch_bounds__(256, 2)
k_gemm_bf16(int a0_id, int a1_id, int Ka, int b_id,
            const float* __restrict__ bias,
            int outb_id,          // >=0: bf16 out buffer id; <0: split bf16/fp32 out
            int M, int N, int K2, int do_relu) {
    const __nv_bfloat16* A0 = bbuf(a0_id);
    const __nv_bfloat16* A1 = bbuf(a1_id);
    const __nv_bfloat16* Bt = bbuf(b_id);
    const int sA0 = Ka, sA1 = K2 - Ka;

    constexpr int BM = 128, BN = 128, BK = 32;
    extern __shared__ __nv_bfloat16 dsm[];
    __nv_bfloat16* AsB = dsm;                     // 3 * 128*SA
    __nv_bfloat16* BsB = dsm + 3 * BM * SA;       // 3 * 128*SA

    const int tid  = threadIdx.x;
    const int lane = tid & 31;
    const int warp = tid >> 5;
    const int wm   = warp & 3;
    const int wn   = warp >> 2;
    const int gid  = lane >> 2;
    const int tig  = lane & 3;

    const int blockRow = blockIdx.x * BM;
    const int blockCol = blockIdx.y * BN;

    float c[2][8][4];
#pragma unroll
    for (int mt = 0; mt < 2; mt++)
#pragma unroll
        for (int nt = 0; nt < 8; nt++)
#pragma unroll
            for (int r = 0; r < 4; r++) c[mt][nt][r] = 0.f;

    const int T = K2 / BK;

    auto load_tile = [&](int t, int stg) {
        __nv_bfloat16* As = AsB + stg * BM * SA;
        __nv_bfloat16* Bs = BsB + stg * BN * SA;
        const int kk = t * BK;
#pragma unroll
        for (int j = 0; j < 2; j++) {
            int f = tid + 256 * j;
            int r = f >> 2, c16 = f & 3;
            int gk = kk + c16 * 8;
            int grow = blockRow + r;
            int valid = grow < M;
            int rr = valid ? grow : 0;
            const __nv_bfloat16* p = (gk < Ka) ? (A0 + (size_t)rr * sA0 + gk)
                                               : (A1 + (size_t)rr * sA1 + (gk - Ka));
            cpa16(&As[r * SA + c16 * 8], p, valid);
        }
#pragma unroll
        for (int j = 0; j < 2; j++) {
            int f = tid + 256 * j;
            int r = f >> 2, c16 = f & 3;
            int gk = kk + c16 * 8;
            cpa16(&Bs[r * SA + c16 * 8], Bt + (size_t)(blockCol + r) * K2 + gk, 1);
        }
        asm volatile("cp.async.commit_group;\n");
    };

    load_tile(0, 0);
    if (T > 1) load_tile(1, 1);

    for (int t = 0; t < T; t++) {
        if (t + 1 < T) {
            asm volatile("cp.async.wait_group 1;\n");
        } else {
            asm volatile("cp.async.wait_group 0;\n");
        }
        __syncthreads();

        const int cur = t % 3;
        const __nv_bfloat16* as = AsB + cur * BM * SA;
        const __nv_bfloat16* bs = BsB + cur * BN * SA;

#pragma unroll
        for (int ks = 0; ks < BK; ks += 16) {
            unsigned af[2][4], bf[8][2];
#pragma unroll
            for (int mt = 0; mt < 2; mt++) {
                int row = wm * 32 + mt * 16 + (lane & 15);
                unsigned sa = (unsigned)__cvta_generic_to_shared(
                    as + row * SA + ks + (lane >> 4) * 8);
                asm volatile("ldmatrix.sync.aligned.m8n8.x4.shared.b16 {%0,%1,%2,%3}, [%4];"
                             : "=r"(af[mt][0]), "=r"(af[mt][1]),
                               "=r"(af[mt][2]), "=r"(af[mt][3])
                             : "r"(sa));
            }
#pragma unroll
            for (int np = 0; np < 4; np++) {
                int nrow = wn * 64 + np * 16 + (lane & 15);
                unsigned sb = (unsigned)__cvta_generic_to_shared(
                    bs + nrow * SA + ks + (lane >> 4) * 8);
                unsigned r0, r1, r2, r3;
                asm volatile("ldmatrix.sync.aligned.m8n8.x4.shared.b16 {%0,%1,%2,%3}, [%4];"
                             : "=r"(r0), "=r"(r1), "=r"(r2), "=r"(r3)
                             : "r"(sb));
                bf[2 * np + 0][0] = r0; bf[2 * np + 0][1] = r2;
                bf[2 * np + 1][0] = r1; bf[2 * np + 1][1] = r3;
            }
#pragma unroll
            for (int mt = 0; mt < 2; mt++)
#pragma unroll
                for (int nt = 0; nt < 8; nt++) {
                    asm volatile(
                        "mma.sync.aligned.m16n8k16.row.col.f32.bf16.bf16.f32 "
                        "{%0,%1,%2,%3}, {%4,%5,%6,%7}, {%8,%9}, {%0,%1,%2,%3};\n"
                        : "+f"(c[mt][nt][0]), "+f"(c[mt][nt][1]),
                          "+f"(c[mt][nt][2]), "+f"(c[mt][nt][3])
                        : "r"(af[mt][0]), "r"(af[mt][1]), "r"(af[mt][2]), "r"(af[mt][3]),
                          "r"(bf[nt][0]), "r"(bf[nt][1]));
                }
        }

        if (t + 2 < T) load_tile(t + 2, (t + 2) % 3);
    }

    // epilogue
    __nv_bfloat16* outb = (outb_id >= 0) ? bbuf(outb_id) : nullptr;
    const int half = N >> 1;
#pragma unroll
    for (int nt = 0; nt < 8; nt++) {
        int col = blockCol + wn * 64 + nt * 8 + 2 * tig;
        float bv0 = bias ? bias[col] : 0.f;
        float bv1 = bias ? bias[col + 1] : 0.f;
#pragma unroll
        for (int mt = 0; mt < 2; mt++) {
#pragma unroll
            for (int h = 0; h < 2; h++) {
                int r = blockRow + wm * 32 + mt * 16 + gid + h * 8;
                if (r < M) {
                    float v0 = c[mt][nt][2 * h + 0] + bv0;
                    float v1 = c[mt][nt][2 * h + 1] + bv1;
                    if (do_relu) { v0 = fmaxf(v0, 0.f); v1 = fmaxf(v1, 0.f); }
                    if (outb) {
                        __nv_bfloat162 o;
                        o.x = __float2bfloat16(v0);
                        o.y = __float2bfloat16(v1);
                        *(unsigned*)(outb + (size_t)r * N + col) =
                            *reinterpret_cast<unsigned*>(&o);
                    } else if (col < half) {
                        // mean-term (Wl half): bf16
                        __nv_bfloat162 o;
                        o.x = __float2bfloat16(v0);
                        o.y = __float2bfloat16(v1);
                        *(unsigned*)(g_tb + (size_t)r * half + col) =
                            *reinterpret_cast<unsigned*>(&o);
                    } else {
                        // self-term (Wr half): fp32
                        float2 o = make_float2(v0, v1);
                        *(float2*)(g_t + (size_t)r * half + (col - half)) = o;
                    }
                }
            }
        }
    }
}

// ---------------- agg-combine: h = act(mean_nb(tb) + t_self + bias) ----------------
template <int C, int MODE>
__global__ void k_agg_combine(const float* __restrict__ bias, float* __restrict__ out) {
    int gw   = (blockIdx.x * blockDim.x + threadIdx.x) >> 5;
    int lane = threadIdx.x & 31;
    if (gw >= NN) return;
    int s = g_rowstart[gw], e = g_rowstart[gw + 1];

    if (MODE == 0) {   // C=128, relu -> bf16 g_h2b
        float4 acc = make_float4(0.f, 0.f, 0.f, 0.f);
        for (int i = s; i < e; i++) {
            int nb = g_col[i];
            uint2 v = *(const uint2*)(g_tb + (size_t)nb * C + lane * 4);
            __nv_bfloat162 p0 = *reinterpret_cast<__nv_bfloat162*>(&v.x);
            __nv_bfloat162 p1 = *reinterpret_cast<__nv_bfloat162*>(&v.y);
            float2 f0 = __bfloat1622float2(p0);
            float2 f1 = __bfloat1622float2(p1);
            acc.x += f0.x; acc.y += f0.y; acc.z += f1.x; acc.w += f1.y;
        }
        float inv = 1.0f / (float)max(e - s, 1);
        float4 sv = *(const float4*)(g_t + (size_t)gw * C + lane * 4);
        float4 bv = *(const float4*)(bias + lane * 4);
        float v0 = fmaxf(acc.x * inv + sv.x + bv.x, 0.f);
        float v1 = fmaxf(acc.y * inv + sv.y + bv.y, 0.f);
        float v2 = fmaxf(acc.z * inv + sv.z + bv.z, 0.f);
        float v3 = fmaxf(acc.w * inv + sv.w + bv.w, 0.f);
        __nv_bfloat162 o0, o1;
        o0.x = __float2bfloat16(v0); o0.y = __float2bfloat16(v1);
        o1.x = __float2bfloat16(v2); o1.y = __float2bfloat16(v3);
        uint2 ov;
        ov.x = *reinterpret_cast<unsigned*>(&o0);
        ov.y = *reinterpret_cast<unsigned*>(&o1);
        *(uint2*)(g_h2b + (size_t)gw * C + lane * 4) = ov;
    } else {           // C=64, log_softmax -> fp32 out
        float2 acc = make_float2(0.f, 0.f);
        for (int i = s; i < e; i++) {
            int nb = g_col[i];
            unsigned v = *(const unsigned*)(g_tb + (size_t)nb * C + lane * 2);
            __nv_bfloat162 p = *reinterpret_cast<__nv_bfloat162*>(&v);
            float2 f = __bfloat1622float2(p);
            acc.x += f.x; acc.y += f.y;
        }
        float inv = 1.0f / (float)max(e - s, 1);
        float2 sv = *(const float2*)(g_t + (size_t)gw * C + lane * 2);
        float2 bv = *(const float2*)(bias + lane * 2);
        float v0 = acc.x * inv + sv.x + bv.x;
        float v1 = acc.y * inv + sv.y + bv.y;
        float m = fmaxf(v0, v1);
#pragma unroll
        for (int off = 16; off; off >>= 1) m = fmaxf(m, __shfl_xor_sync(0xffffffffu, m, off));
        float sum = __expf(v0 - m) + __expf(v1 - m);
#pragma unroll
        for (int off = 16; off; off >>= 1) sum += __shfl_xor_sync(0xffffffffu, sum, off);
        float lse = m + __logf(sum);
        float2 o = make_float2(v0 - lse, v1 - lse);
        *(float2*)(out + (size_t)gw * C + lane * 2) = o;
    }
}

// ---------------- launch ----------------
extern "C" void kernel_launch(void* const* d_in, const int* in_sizes, int n_in,
                              void* d_out, int out_size) {
    const float* x   = (const float*)d_in[0];
    const int*   ei  = (const int*)d_in[1];
    const float* W1l = (const float*)d_in[2];
    const float* W1r = (const float*)d_in[3];
    const float* b1  = (const float*)d_in[4];
    const float* W2l = (const float*)d_in[5];
    const float* W2r = (const float*)d_in[6];
    const float* b2  = (const float*)d_in[7];
    const float* W3l = (const float*)d_in[8];
    const float* W3r = (const float*)d_in[9];
    const float* b3  = (const float*)d_in[10];
    float* out = (float*)d_out;

    int E = in_sizes[1] / 2;

    static cudaStream_t s1 = nullptr, s2 = nullptr;
    static cudaEvent_t eFork = nullptr, eCvtX = nullptr, eCvtW = nullptr;
    if (!s1) {
        cudaStreamCreateWithFlags(&s1, cudaStreamNonBlocking);
        cudaStreamCreateWithFlags(&s2, cudaStreamNonBlocking);
        cudaEventCreateWithFlags(&eFork, cudaEventDisableTiming);
        cudaEventCreateWithFlags(&eCvtX, cudaEventDisableTiming);
        cudaEventCreateWithFlags(&eCvtW, cudaEventDisableTiming);
        cudaFuncSetAttribute(k_gemm_bf16,
                             cudaFuncAttributeMaxDynamicSharedMemorySize, GEMM_SMEM);
    }

    // fork
    cudaEventRecord(eFork, 0);
    cudaStreamWaitEvent(s1, eFork, 0);
    cudaStreamWaitEvent(s2, eFork, 0);

    // s1: x -> bf16
    k_cvt_x<<<(NN * 32 + 255) / 256, 256, 0, s1>>>(x);
    cudaEventRecord(eCvtX, s1);

    // s2: weight transposes -> bf16
    k_cvtw<<<(256 * 256 + 255) / 256, 256, 0, s2>>>(W1l, W1r, 4, 256, 256, 1);
    k_cvtw<<<(256 * 256 + 255) / 256, 256, 0, s2>>>(W2l, W2r, 5, 256, 256, 0);
    k_cvtw<<<(128 * 128 + 255) / 256, 256, 0, s2>>>(W3l, W3r, 6, 128, 128, 0);
    cudaEventRecord(eCvtW, s2);

    // main stream: CSR build
    k_init<<<(NN + 255) / 256, 256>>>(ei);
    k_count<<<(E + 255) / 256, 256>>>(ei, E);
    k_part_sum<<<NB_SCAN, 256>>>();
    k_row_write<<<NB_SCAN, 256>>>(E);
    k_fill<<<(E + 255) / 256, 256>>>(ei, E);

    cudaStreamWaitEvent(0, eCvtX, 0);

    int aggBlocks = (NN * 32 + 255) / 256;

    // Layer 1: pre-agg + dual-A GEMM -> h1b (relu)
    k_agg_pre<<<aggBlocks, 256>>>();
    cudaStreamWaitEvent(0, eCvtW, 0);
    {
        dim3 grid((NN + 127) / 128, 256 / 128);
        k_gemm_bf16<<<grid, 256, GEMM_SMEM>>>(1, 0, 128, 4, b1, /*outb=*/2, NN, 256, 256, 1);
    }
    // Layer 2: GEMM -> split tb/t, agg-combine(relu) -> h2b
    {
        dim3 grid((NN + 127) / 128, 256 / 128);
        k_gemm_bf16<<<grid, 256, GEMM_SMEM>>>(2, 2, 256, 5, nullptr, /*outb=*/-1, NN, 256, 256, 0);
    }
    k_agg_combine<128, 0><<<aggBlocks, 256>>>(b2, nullptr);
    // Layer 3: GEMM -> split tb/t, agg-combine + log_softmax -> out
    {
        dim3 grid((NN + 127) / 128, 128 / 128);
        k_gemm_bf16<<<grid, 256, GEMM_SMEM>>>(3, 3, 128, 6, nullptr, /*outb=*/-1, NN, 128, 128, 0);
    }
    k_agg_combine<64, 1><<<aggBlocks, 256>>>(b3, out);
}